// round 10
// baseline (speedup 1.0000x reference)
#include <cuda_runtime.h>
#include <math.h>

#define B_  32
#define S_  512
#define I_  256
#define H_  1024
#define O_  256
#define L_  3
#define G3H (3*H_)
#define M_TOT (S_*B_)
#define NCTA_REC 128

typedef unsigned long long ull;

// ---------------- f32x2 packed math (sm_103a FFMA2 path) ----------------
__device__ __forceinline__ ull pk2(float x, float y) {
    ull r;
    asm("mov.b64 %0, {%1, %2};" : "=l"(r)
        : "r"(__float_as_uint(x)), "r"(__float_as_uint(y)));
    return r;
}
__device__ __forceinline__ void upk2(ull p, float& x, float& y) {
    unsigned int a, b;
    asm("mov.b64 {%0, %1}, %2;" : "=r"(a), "=r"(b) : "l"(p));
    x = __uint_as_float(a); y = __uint_as_float(b);
}
__device__ __forceinline__ ull ffma2(ull a, ull b, ull c) {
    ull d;
    asm("fma.rn.f32x2 %0, %1, %2, %3;" : "=l"(d) : "l"(a), "l"(b), "l"(c));
    return d;
}
__device__ __forceinline__ ull fadd2(ull a, ull b) {
    ull d;
    asm("add.rn.f32x2 %0, %1, %2;" : "=l"(d) : "l"(a), "l"(b));
    return d;
}

// ---------------- device scratch (allocation-free) ----------------
__device__ float g_xT[(size_t)M_TOT*I_];        // 16 MB  transposed x -> [s*B+b][i]
__device__ float g_xpT[(size_t)G3H*M_TOT];      // 201 MB xproj TRANSPOSED [col][s*B+b]
__device__ float g_hs[(size_t)M_TOT*H_];        // 64 MB  layer output sequence [s*B+b][h]
__device__ ull   g_hP [(H_/2)*B_];              // hidden, [kpair][b] packed f32x2
__device__ ull   g_rhP[(H_/2)*B_];              // r*h,    [kpair][b] packed f32x2
__device__ __align__(16) unsigned int g_flags[NCTA_REC];   // barrier flags

// ---------------- grid barrier: per-CTA epoch flags, warp-0 poll ----------------
// Arrival = 128 PARALLEL stores to distinct lines (no atomic serialization).
// Fence discipline identical to the proven atomic barrier: one release fence
// (thread 0) before arrival, one fence after the poll completes.
// Epochs are strictly increasing within a launch (ebase per layer); flags are
// memset to 0 before the launches, so ">=" comparisons are safe.
__device__ __forceinline__ void grid_barrier(unsigned int epoch, int w, int lane)
{
    __syncthreads();
    if (threadIdx.x == 0) {
        __threadfence();
        ((volatile unsigned int*)g_flags)[blockIdx.x] = epoch;
    }
    if (w == 0) {
        const uint4* f4 = (const uint4*)g_flags;
        for (;;) {
            uint4 v = __ldcg(&f4[lane]);          // 32 lanes x 4 = 128 flags
            bool ok = (v.x >= epoch) & (v.y >= epoch) &
                      (v.z >= epoch) & (v.w >= epoch);
            if (__all_sync(0xffffffffu, ok)) break;
            __nanosleep(32);
        }
        __threadfence();
    }
    __syncthreads();
}

// ---------------- transpose x[b][s][i] -> xT[(s*B+b)][i] ----------------
__global__ void transpose_kernel(const float4* __restrict__ x, float4* __restrict__ xT)
{
    int idx = blockIdx.x * blockDim.x + threadIdx.x;   // over S*B*I/4
    int i4 = idx & 63;          // I/4 = 64
    int m  = idx >> 6;          // m = s*B + b
    int b  = m & 31;
    int s  = m >> 5;
    xT[idx] = x[(size_t)(b * S_ + s) * 64 + i4];
}

// ---------------- SGEMM: C = A*W^T + bias, double-buffered smem ----------------
// mode 0: write TRANSPOSED  C_T[n][m]   (xproj -> g_xpT)
// mode 1: m=(s*B+b) -> C[(b*S+s)*O + n] (final output head)
__global__ void __launch_bounds__(256) gemm_kernel(
    const float* __restrict__ A, const float* __restrict__ W,
    const float* __restrict__ bias, float* __restrict__ C,
    int K, int N, int mode)
{
    __shared__ float As[2][16][128];
    __shared__ float Bs[2][16][128];

    const int tid  = threadIdx.x;
    const int bx   = blockIdx.x;   // N tile
    const int by   = blockIdx.y;   // M tile
    const int lrow = tid >> 1;
    const int lc4  = (tid & 1) << 2;

    const float* Arow = A + (size_t)(by * 128 + lrow) * K + lc4;
    const float* Wrow = W + (size_t)(bx * 128 + lrow) * K + lc4;

    const int tx = tid & 15;
    const int ty = tid >> 4;

    ull acc2[8][4];
#pragma unroll
    for (int i = 0; i < 8; i++)
#pragma unroll
        for (int j = 0; j < 4; j++) acc2[i][j] = 0ull;

    // prologue: tile 0 -> buf 0
    {
        float4 a0 = *(const float4*)(Arow);
        float4 a1 = *(const float4*)(Arow + 8);
        float4 w0 = *(const float4*)(Wrow);
        float4 w1 = *(const float4*)(Wrow + 8);
        As[0][lc4 + 0][lrow] = a0.x; As[0][lc4 + 1][lrow] = a0.y;
        As[0][lc4 + 2][lrow] = a0.z; As[0][lc4 + 3][lrow] = a0.w;
        As[0][lc4 + 8][lrow] = a1.x; As[0][lc4 + 9][lrow] = a1.y;
        As[0][lc4 +10][lrow] = a1.z; As[0][lc4 +11][lrow] = a1.w;
        Bs[0][lc4 + 0][lrow] = w0.x; Bs[0][lc4 + 1][lrow] = w0.y;
        Bs[0][lc4 + 2][lrow] = w0.z; Bs[0][lc4 + 3][lrow] = w0.w;
        Bs[0][lc4 + 8][lrow] = w1.x; Bs[0][lc4 + 9][lrow] = w1.y;
        Bs[0][lc4 +10][lrow] = w1.z; Bs[0][lc4 +11][lrow] = w1.w;
    }
    __syncthreads();

    int p = 0;
    for (int kt = 0; kt < K; kt += 16) {
        const bool nxt = (kt + 16) < K;
        float4 a0, a1, w0, w1;
        if (nxt) {                               // issue next-tile loads early
            a0 = *(const float4*)(Arow + kt + 16);
            a1 = *(const float4*)(Arow + kt + 24);
            w0 = *(const float4*)(Wrow + kt + 16);
            w1 = *(const float4*)(Wrow + kt + 24);
        }
#pragma unroll
        for (int k = 0; k < 16; k++) {
            float4 av0 = *(const float4*)&As[p][k][ty * 8];
            float4 av1 = *(const float4*)&As[p][k][ty * 8 + 4];
            // b-operands come out of smem ALREADY packed as f32x2 pairs
            ulonglong2 b01 = *(const ulonglong2*)&Bs[p][k][tx * 8];
            ulonglong2 b23 = *(const ulonglong2*)&Bs[p][k][tx * 8 + 4];
            ull pb0 = b01.x, pb1 = b01.y, pb2 = b23.x, pb3 = b23.y;
            float a_[8] = {av0.x, av0.y, av0.z, av0.w, av1.x, av1.y, av1.z, av1.w};
#pragma unroll
            for (int i = 0; i < 8; i++) {
                ull pa = pk2(a_[i], a_[i]);
                acc2[i][0] = ffma2(pa, pb0, acc2[i][0]);
                acc2[i][1] = ffma2(pa, pb1, acc2[i][1]);
                acc2[i][2] = ffma2(pa, pb2, acc2[i][2]);
                acc2[i][3] = ffma2(pa, pb3, acc2[i][3]);
            }
        }
        if (nxt) {
            const int q = p ^ 1;
            As[q][lc4 + 0][lrow] = a0.x; As[q][lc4 + 1][lrow] = a0.y;
            As[q][lc4 + 2][lrow] = a0.z; As[q][lc4 + 3][lrow] = a0.w;
            As[q][lc4 + 8][lrow] = a1.x; As[q][lc4 + 9][lrow] = a1.y;
            As[q][lc4 +10][lrow] = a1.z; As[q][lc4 +11][lrow] = a1.w;
            Bs[q][lc4 + 0][lrow] = w0.x; Bs[q][lc4 + 1][lrow] = w0.y;
            Bs[q][lc4 + 2][lrow] = w0.z; Bs[q][lc4 + 3][lrow] = w0.w;
            Bs[q][lc4 + 8][lrow] = w1.x; Bs[q][lc4 + 9][lrow] = w1.y;
            Bs[q][lc4 +10][lrow] = w1.z; Bs[q][lc4 +11][lrow] = w1.w;
            __syncthreads();
            p = q;
        }
    }

    const int mbase = by * 128 + ty * 8;
    const int nbase = bx * 128 + tx * 8;
    float bb[8];
#pragma unroll
    for (int j = 0; j < 8; j++) bb[j] = bias[nbase + j];

#pragma unroll
    for (int i = 0; i < 8; i++) {
        int m = mbase + i;
        float cv[8];
#pragma unroll
        for (int j = 0; j < 4; j++) upk2(acc2[i][j], cv[2*j], cv[2*j+1]);
#pragma unroll
        for (int j = 0; j < 8; j++) {
            float v = cv[j] + bb[j];
            if (mode == 0) {
                C[(size_t)(nbase + j) * M_TOT + m] = v;      // transposed
            } else {
                int b = m & 31, s = m >> 5;
                C[(size_t)((b << 9) + s) * O_ + (nbase + j)] = v;
            }
        }
    }
}

// ---------------- persistent GRU recurrence (one layer) ----------------
// 128 CTAs (1/SM, co-resident), 512 threads = 16 warps.
// CTA owns gate columns [cta*8, cta*8+8) of z, r, g.
// Warp w = k-slice [w*64, w*64+64). lane = batch b.
// h/r*h in [kpair][b] packed layout (coalesced LDG.64, pre-packed for FFMA2).
// xp in TRANSPOSED [col][m] layout -> epilogue fetches are coalesced too.
__global__ void __launch_bounds__(512, 1) gru_rec_kernel(
    const float* __restrict__ Wh,      // [3H][H]
    const float* __restrict__ xpT,     // [3H][S*B] (bias folded in)
    float*       __restrict__ hs,      // [S*B][H]
    const float* __restrict__ h0,      // [B][L][H]
    int layer,
    float*       __restrict__ hlast,   // d_out + B*S*O : [B][L][H]
    unsigned int ebase)                // barrier epoch base for this launch
{
    extern __shared__ float sh[];
    ull*   ws  = (ull*)sh;             // [24 cols][512 k-pairs]   96 KB
    float* red = sh + 24576;           // [16][32][17] partials    34 KB
    __shared__ float s_z[B_ * 8];      // z values   [b][c]
    __shared__ float s_h[B_ * 8];      // h (own 8 cols) [b][c]

    const int tid  = threadIdx.x;
    const int cta  = blockIdx.x;
    const int w    = tid >> 5;         // 0..15 : k-slice AND epilogue column
    const int lane = tid & 31;         // batch b
    const int j0   = cta * 8;
    const int kp0  = w * 32;           // base k-pair of this warp's slice

    float* hPf  = (float*)g_hP;
    float* rhPf = (float*)g_rhP;

    // ---- preload this CTA's 24 weight rows, packed k-pairs ----
    for (int rr = w; rr < 24; rr += 16) {
        int row = (rr < 8)  ? (j0 + rr)
                : (rr < 16) ? (H_ + j0 + (rr - 8))
                            : (2 * H_ + j0 + (rr - 16));
        const float2* src = (const float2*)(Wh + (size_t)row * H_);
        for (int i = lane; i < 512; i += 32) {
            float2 v = __ldg(src + i);
            ws[rr * 512 + i] = pk2(v.x, v.y);
        }
    }

    // ---- init hidden state: g_hP[(j>>1)*64 + b*2 + (j&1)] (as floats) ----
    {
        int i = cta * 512 + tid;
        if (i < B_ * H_) {
            int b = i >> 10, j = i & 1023;
            hPf[(j >> 1) * 64 + b * 2 + (j & 1)] = h0[(b * L_ + layer) * H_ + j];
        }
        if (w < 8) s_h[lane * 8 + w] = h0[(lane * L_ + layer) * H_ + j0 + w];
    }
    unsigned int ep = ebase;
    grid_barrier(++ep, w, lane);

    // per-thread xp column bases (coalesced: lane-consecutive m)
    const float* xpColA = xpT + (size_t)((w < 8) ? (j0 + w) : (H_ + j0 + (w - 8))) * M_TOT;
    const float* xpColB = (w < 8) ? (xpT + (size_t)(2 * H_ + j0 + w) * M_TOT) : xpT;

    ull v2[32];                        // operand regs, reused between phases

    for (int s = 0; s < S_; s++) {
        // ---- prefetch xp for this thread's epilogue column (coalesced) ----
        const int m = s * B_ + lane;
        float xpA = __ldg(xpColA + m);
        float xpB = (w < 8) ? __ldg(xpColB + m) : 0.f;

        // ---- load h k-slice: 32 coalesced LDG.64, already packed ----
        {
            const ull* hp = g_hP + (size_t)kp0 * 32 + lane;
#pragma unroll
            for (int i = 0; i < 32; i++)
                v2[i] = __ldcg(hp + i * 32);
        }

        // ---- phase A: 16 cols (8 z + 8 r), this warp's 64 k ----
#pragma unroll 2
        for (int c = 0; c < 16; c++) {
            const ulonglong2* wp = (const ulonglong2*)(ws + c * 512 + kp0);
            ull a0 = 0, a1 = 0;
#pragma unroll
            for (int i = 0; i < 16; i++) {
                ulonglong2 u = wp[i];
                a0 = ffma2(v2[2*i],   u.x, a0);
                a1 = ffma2(v2[2*i+1], u.y, a1);
            }
            a0 = fadd2(a0, a1);
            float x, y; upk2(a0, x, y);
            red[(c * 32 + lane) * 17 + w] = x + y;
        }
        __syncthreads();

        // ---- reduce + gate epilogue: thread (c=w, b=lane) ----
        {
            const float* rp = red + (w * 32 + lane) * 17;
            float sum = xpA;
#pragma unroll
            for (int t = 0; t < 16; t++) sum += rp[t];
            float sg = 1.f / (1.f + expf(-sum));
            if (w < 8) {
                s_z[lane * 8 + w] = sg;
            } else {
                int c = w - 8;
                int j = j0 + c;
                rhPf[(j >> 1) * 64 + lane * 2 + (j & 1)] = sg * s_h[lane * 8 + c];
            }
        }
        grid_barrier(++ep, w, lane);

        // ---- load rh k-slice (reuses v2) ----
        {
            const ull* rp8 = g_rhP + (size_t)kp0 * 32 + lane;
#pragma unroll
            for (int i = 0; i < 32; i++)
                v2[i] = __ldcg(rp8 + i * 32);
        }

        // ---- phase B: 8 g cols ----
#pragma unroll 2
        for (int c = 0; c < 8; c++) {
            const ulonglong2* wp = (const ulonglong2*)(ws + (16 + c) * 512 + kp0);
            ull a0 = 0, a1 = 0;
#pragma unroll
            for (int i = 0; i < 16; i++) {
                ulonglong2 u = wp[i];
                a0 = ffma2(v2[2*i],   u.x, a0);
                a1 = ffma2(v2[2*i+1], u.y, a1);
            }
            a0 = fadd2(a0, a1);
            float x, y; upk2(a0, x, y);
            red[(c * 32 + lane) * 17 + w] = x + y;
        }
        __syncthreads();

        // ---- reduce + h update: thread (c=w<8, b=lane) ----
        if (w < 8) {
            const float* rp = red + (w * 32 + lane) * 17;
            float sum = xpB;
#pragma unroll
            for (int t = 0; t < 16; t++) sum += rp[t];
            float gg = tanhf(sum);
            float zz = s_z[lane * 8 + w];
            float ho = s_h[lane * 8 + w];
            float hn = zz * ho + (1.f - zz) * gg;
            int j = j0 + w;
            s_h[lane * 8 + w] = hn;
            hPf[(j >> 1) * 64 + lane * 2 + (j & 1)] = hn;
            hs[(size_t)(s * B_ + lane) * H_ + j] = hn;
            if (s == S_ - 1) hlast[(size_t)(lane * L_ + layer) * H_ + j] = hn;
        }
        grid_barrier(++ep, w, lane);
    }
}

// ---------------- host launch ----------------
extern "C" void kernel_launch(void* const* d_in, const int* in_sizes, int n_in,
                              void* d_out, int out_size)
{
    const float* x    = (const float*)d_in[0];
    const float* h0   = (const float*)d_in[1];
    const float* Wx0  = (const float*)d_in[2];
    const float* Wh0  = (const float*)d_in[3];
    const float* bh0  = (const float*)d_in[4];
    const float* Wx   = (const float*)d_in[5];
    const float* Wh   = (const float*)d_in[6];
    const float* bh   = (const float*)d_in[7];
    const float* Wout = (const float*)d_in[8];
    const float* bout = (const float*)d_in[9];

    float* out = (float*)d_out;
    float* hid = out + (size_t)B_ * S_ * O_;

    float *p_xT, *p_xpT, *p_hs;
    cudaGetSymbolAddress((void**)&p_xT, g_xT);
    cudaGetSymbolAddress((void**)&p_xpT, g_xpT);
    cudaGetSymbolAddress((void**)&p_hs, g_hs);

    // reset barrier flags so per-layer epoch bases restart cleanly every call
    unsigned int* p_flags;
    cudaGetSymbolAddress((void**)&p_flags, g_flags);
    cudaMemsetAsync(p_flags, 0, NCTA_REC * sizeof(unsigned int));

    const int rec_smem = 24576 * 4 + 16 * 32 * 17 * 4;   // 98304 + 34816 = 133120
    cudaFuncSetAttribute(gru_rec_kernel,
                         cudaFuncAttributeMaxDynamicSharedMemorySize, rec_smem);

    // 1) transpose x -> [s*B+b][i]
    transpose_kernel<<<4096, 256>>>((const float4*)x, (float4*)p_xT);

    // 2) layer 0
    gemm_kernel<<<dim3(G3H / 128, M_TOT / 128), 256>>>(p_xT, Wx0, bh0, p_xpT, I_, G3H, 0);
    gru_rec_kernel<<<NCTA_REC, 512, rec_smem>>>(Wh0, p_xpT, p_hs, h0, 0, hid, 0u);

    // 3) layer 1
    gemm_kernel<<<dim3(G3H / 128, M_TOT / 128), 256>>>(p_hs, Wx, bh, p_xpT, H_, G3H, 0);
    gru_rec_kernel<<<NCTA_REC, 512, rec_smem>>>(Wh, p_xpT, p_hs, h0, 1, hid, 4096u);

    // 4) layer 2
    gemm_kernel<<<dim3(G3H / 128, M_TOT / 128), 256>>>(
        p_hs, Wx + (size_t)3 * H_ * H_, bh + 3 * H_, p_xpT, H_, G3H, 0);
    gru_rec_kernel<<<NCTA_REC, 512, rec_smem>>>(
        Wh + (size_t)3 * H_ * H_, p_xpT, p_hs, h0, 2, hid, 8192u);

    // 5) output head -> d_out [B,S,O]
    gemm_kernel<<<dim3(O_ / 128, M_TOT / 128), 256>>>(p_hs, Wout, bout, out, H_, O_, 1);
}

// round 11
// speedup vs baseline: 1.5504x; 1.5504x over previous
#include <cuda_runtime.h>
#include <math.h>

#define B_  32
#define S_  512
#define I_  256
#define H_  1024
#define O_  256
#define L_  3
#define G3H (3*H_)
#define M_TOT (S_*B_)
#define NCTA_REC 128

typedef unsigned long long ull;

// ---------------- f32x2 packed math (sm_103a FFMA2 path) ----------------
__device__ __forceinline__ ull pk2(float x, float y) {
    ull r;
    asm("mov.b64 %0, {%1, %2};" : "=l"(r)
        : "r"(__float_as_uint(x)), "r"(__float_as_uint(y)));
    return r;
}
__device__ __forceinline__ void upk2(ull p, float& x, float& y) {
    unsigned int a, b;
    asm("mov.b64 {%0, %1}, %2;" : "=r"(a), "=r"(b) : "l"(p));
    x = __uint_as_float(a); y = __uint_as_float(b);
}
__device__ __forceinline__ ull ffma2(ull a, ull b, ull c) {
    ull d;
    asm("fma.rn.f32x2 %0, %1, %2, %3;" : "=l"(d) : "l"(a), "l"(b), "l"(c));
    return d;
}
__device__ __forceinline__ ull fadd2(ull a, ull b) {
    ull d;
    asm("add.rn.f32x2 %0, %1, %2;" : "=l"(d) : "l"(a), "l"(b));
    return d;
}

// ---------------- device scratch (allocation-free) ----------------
__device__ float g_xT[(size_t)M_TOT*I_];        // 16 MB  transposed x -> [s*B+b][i]
__device__ float g_xpT[(size_t)G3H*M_TOT];      // 201 MB xproj TRANSPOSED [col][s*B+b]
__device__ float g_hs[(size_t)M_TOT*H_];        // 64 MB  layer output sequence [s*B+b][h]
__device__ ull   g_hP [(H_/2)*B_];              // hidden, [kpair][b] packed f32x2
__device__ ull   g_rhP[(H_/2)*B_];              // r*h,    [kpair][b] packed f32x2
__device__ unsigned int g_barcount;
__device__ unsigned int g_bargen;

// ---------------- grid-wide barrier (PROVEN atomic version — do not touch) ----------------
__device__ __forceinline__ void grid_barrier()
{
    __syncthreads();
    if (threadIdx.x == 0) {
        unsigned int gen = *(volatile unsigned int*)&g_bargen;
        __threadfence();
        if (atomicAdd(&g_barcount, 1u) == gridDim.x - 1u) {
            g_barcount = 0u;
            __threadfence();
            atomicAdd(&g_bargen, 1u);
        } else {
            while (*(volatile unsigned int*)&g_bargen == gen) { __nanosleep(32); }
        }
        __threadfence();
    }
    __syncthreads();
}

// ---------------- transpose x[b][s][i] -> xT[(s*B+b)][i] ----------------
__global__ void transpose_kernel(const float4* __restrict__ x, float4* __restrict__ xT)
{
    int idx = blockIdx.x * blockDim.x + threadIdx.x;   // over S*B*I/4
    int i4 = idx & 63;          // I/4 = 64
    int m  = idx >> 6;          // m = s*B + b
    int b  = m & 31;
    int s  = m >> 5;
    xT[idx] = x[(size_t)(b * S_ + s) * 64 + i4];
}

// ---------------- SGEMM: C = A*W^T + bias, double-buffered smem ----------------
// A staged DUPLICATED (each value twice adjacently) so a-operands come out of
// LDS.128 already packed (a,a) for FFMA2 — no pk2 MOVs in the inner loop.
// mode 0: write TRANSPOSED  C_T[n][m]   (xproj -> g_xpT)
// mode 1: m=(s*B+b) -> C[(b*S+s)*O + n] (final output head)
__global__ void __launch_bounds__(256) gemm_kernel(
    const float* __restrict__ A, const float* __restrict__ W,
    const float* __restrict__ bias, float* __restrict__ C,
    int K, int N, int mode)
{
    __shared__ float As[2][16][256];   // duplicated pairs: 32 KB
    __shared__ float Bs[2][16][128];   // 16 KB

    const int tid  = threadIdx.x;
    const int bx   = blockIdx.x;   // N tile
    const int by   = blockIdx.y;   // M tile
    const int lrow = tid >> 1;
    const int lc4  = (tid & 1) << 2;

    const float* Arow = A + (size_t)(by * 128 + lrow) * K + lc4;
    const float* Wrow = W + (size_t)(bx * 128 + lrow) * K + lc4;

    const int tx = tid & 15;
    const int ty = tid >> 4;

    ull acc2[8][4];
#pragma unroll
    for (int i = 0; i < 8; i++)
#pragma unroll
        for (int j = 0; j < 4; j++) acc2[i][j] = 0ull;

    // prologue: tile 0 -> buf 0
    {
        float4 a0 = *(const float4*)(Arow);
        float4 a1 = *(const float4*)(Arow + 8);
        float4 w0 = *(const float4*)(Wrow);
        float4 w1 = *(const float4*)(Wrow + 8);
        *(float2*)&As[0][lc4 + 0][lrow*2] = make_float2(a0.x, a0.x);
        *(float2*)&As[0][lc4 + 1][lrow*2] = make_float2(a0.y, a0.y);
        *(float2*)&As[0][lc4 + 2][lrow*2] = make_float2(a0.z, a0.z);
        *(float2*)&As[0][lc4 + 3][lrow*2] = make_float2(a0.w, a0.w);
        *(float2*)&As[0][lc4 + 8][lrow*2] = make_float2(a1.x, a1.x);
        *(float2*)&As[0][lc4 + 9][lrow*2] = make_float2(a1.y, a1.y);
        *(float2*)&As[0][lc4 +10][lrow*2] = make_float2(a1.z, a1.z);
        *(float2*)&As[0][lc4 +11][lrow*2] = make_float2(a1.w, a1.w);
        Bs[0][lc4 + 0][lrow] = w0.x; Bs[0][lc4 + 1][lrow] = w0.y;
        Bs[0][lc4 + 2][lrow] = w0.z; Bs[0][lc4 + 3][lrow] = w0.w;
        Bs[0][lc4 + 8][lrow] = w1.x; Bs[0][lc4 + 9][lrow] = w1.y;
        Bs[0][lc4 +10][lrow] = w1.z; Bs[0][lc4 +11][lrow] = w1.w;
    }
    __syncthreads();

    int p = 0;
    for (int kt = 0; kt < K; kt += 16) {
        const bool nxt = (kt + 16) < K;
        float4 a0, a1, w0, w1;
        if (nxt) {                               // issue next-tile loads early
            a0 = *(const float4*)(Arow + kt + 16);
            a1 = *(const float4*)(Arow + kt + 24);
            w0 = *(const float4*)(Wrow + kt + 16);
            w1 = *(const float4*)(Wrow + kt + 24);
        }
#pragma unroll
        for (int k = 0; k < 16; k++) {
            // a-operands: already-duplicated packed pairs (broadcast LDS.128)
            ulonglong2 pa01 = *(const ulonglong2*)&As[p][k][ty * 16];
            ulonglong2 pa23 = *(const ulonglong2*)&As[p][k][ty * 16 + 4];
            ulonglong2 pa45 = *(const ulonglong2*)&As[p][k][ty * 16 + 8];
            ulonglong2 pa67 = *(const ulonglong2*)&As[p][k][ty * 16 + 12];
            // b-operands: packed f32x2 pairs straight from smem
            ulonglong2 b01 = *(const ulonglong2*)&Bs[p][k][tx * 8];
            ulonglong2 b23 = *(const ulonglong2*)&Bs[p][k][tx * 8 + 4];
            ull pb0 = b01.x, pb1 = b01.y, pb2 = b23.x, pb3 = b23.y;
            ull pa[8] = {pa01.x, pa01.y, pa23.x, pa23.y,
                         pa45.x, pa45.y, pa67.x, pa67.y};
#pragma unroll
            for (int i = 0; i < 8; i++) {
                acc2[i][0] = ffma2(pa[i], pb0, acc2[i][0]);
                acc2[i][1] = ffma2(pa[i], pb1, acc2[i][1]);
                acc2[i][2] = ffma2(pa[i], pb2, acc2[i][2]);
                acc2[i][3] = ffma2(pa[i], pb3, acc2[i][3]);
            }
        }
        if (nxt) {
            const int q = p ^ 1;
            *(float2*)&As[q][lc4 + 0][lrow*2] = make_float2(a0.x, a0.x);
            *(float2*)&As[q][lc4 + 1][lrow*2] = make_float2(a0.y, a0.y);
            *(float2*)&As[q][lc4 + 2][lrow*2] = make_float2(a0.z, a0.z);
            *(float2*)&As[q][lc4 + 3][lrow*2] = make_float2(a0.w, a0.w);
            *(float2*)&As[q][lc4 + 8][lrow*2] = make_float2(a1.x, a1.x);
            *(float2*)&As[q][lc4 + 9][lrow*2] = make_float2(a1.y, a1.y);
            *(float2*)&As[q][lc4 +10][lrow*2] = make_float2(a1.z, a1.z);
            *(float2*)&As[q][lc4 +11][lrow*2] = make_float2(a1.w, a1.w);
            Bs[q][lc4 + 0][lrow] = w0.x; Bs[q][lc4 + 1][lrow] = w0.y;
            Bs[q][lc4 + 2][lrow] = w0.z; Bs[q][lc4 + 3][lrow] = w0.w;
            Bs[q][lc4 + 8][lrow] = w1.x; Bs[q][lc4 + 9][lrow] = w1.y;
            Bs[q][lc4 +10][lrow] = w1.z; Bs[q][lc4 +11][lrow] = w1.w;
            __syncthreads();
            p = q;
        }
    }

    const int mbase = by * 128 + ty * 8;
    const int nbase = bx * 128 + tx * 8;
    float bb[8];
#pragma unroll
    for (int j = 0; j < 8; j++) bb[j] = bias[nbase + j];

#pragma unroll
    for (int i = 0; i < 8; i++) {
        int m = mbase + i;
        float cv[8];
#pragma unroll
        for (int j = 0; j < 4; j++) upk2(acc2[i][j], cv[2*j], cv[2*j+1]);
#pragma unroll
        for (int j = 0; j < 8; j++) {
            float v = cv[j] + bb[j];
            if (mode == 0) {
                C[(size_t)(nbase + j) * M_TOT + m] = v;      // transposed
            } else {
                int b = m & 31, s = m >> 5;
                C[(size_t)((b << 9) + s) * O_ + (nbase + j)] = v;
            }
        }
    }
}

// ---------------- persistent GRU recurrence (one layer) ----------------
// 128 CTAs (1/SM, co-resident), 512 threads = 16 warps.
// CTA owns gate columns [cta*8, cta*8+8) of z, r, g.
// Warp w = k-slice [w*64, w*64+64). lane = batch b.
// h/r*h in [kpair][b] packed layout (coalesced LDG.64, pre-packed for FFMA2).
// xp in TRANSPOSED [col][m] layout -> epilogue fetches are coalesced too.
__global__ void __launch_bounds__(512, 1) gru_rec_kernel(
    const float* __restrict__ Wh,      // [3H][H]
    const float* __restrict__ xpT,     // [3H][S*B] (bias folded in)
    float*       __restrict__ hs,      // [S*B][H]
    const float* __restrict__ h0,      // [B][L][H]
    int layer,
    float*       __restrict__ hlast)   // d_out + B*S*O : [B][L][H]
{
    extern __shared__ float sh[];
    ull*   ws  = (ull*)sh;             // [24 cols][512 k-pairs]   96 KB
    float* red = sh + 24576;           // [16][32][17] partials    34 KB
    __shared__ float s_z[B_ * 8];      // z values   [b][c]
    __shared__ float s_h[B_ * 8];      // h (own 8 cols) [b][c]

    const int tid  = threadIdx.x;
    const int cta  = blockIdx.x;
    const int w    = tid >> 5;         // 0..15 : k-slice AND epilogue column
    const int lane = tid & 31;         // batch b
    const int j0   = cta * 8;
    const int kp0  = w * 32;           // base k-pair of this warp's slice

    float* hPf  = (float*)g_hP;
    float* rhPf = (float*)g_rhP;

    // ---- preload this CTA's 24 weight rows, packed k-pairs ----
    for (int rr = w; rr < 24; rr += 16) {
        int row = (rr < 8)  ? (j0 + rr)
                : (rr < 16) ? (H_ + j0 + (rr - 8))
                            : (2 * H_ + j0 + (rr - 16));
        const float2* src = (const float2*)(Wh + (size_t)row * H_);
        for (int i = lane; i < 512; i += 32) {
            float2 v = __ldg(src + i);
            ws[rr * 512 + i] = pk2(v.x, v.y);
        }
    }

    // ---- init hidden state: g_hP[(j>>1)*64 + b*2 + (j&1)] (as floats) ----
    {
        int i = cta * 512 + tid;
        if (i < B_ * H_) {
            int b = i >> 10, j = i & 1023;
            hPf[(j >> 1) * 64 + b * 2 + (j & 1)] = h0[(b * L_ + layer) * H_ + j];
        }
        if (w < 8) s_h[lane * 8 + w] = h0[(lane * L_ + layer) * H_ + j0 + w];
    }
    grid_barrier();

    // per-thread xp column bases (coalesced: lane-consecutive m)
    const float* xpColA = xpT + (size_t)((w < 8) ? (j0 + w) : (H_ + j0 + (w - 8))) * M_TOT;
    const float* xpColB = (w < 8) ? (xpT + (size_t)(2 * H_ + j0 + w) * M_TOT) : xpT;

    ull v2[32];                        // operand regs, reused between phases

    for (int s = 0; s < S_; s++) {
        // ---- prefetch xp for this thread's epilogue column (coalesced) ----
        const int m = s * B_ + lane;
        float xpA = __ldg(xpColA + m);
        float xpB = (w < 8) ? __ldg(xpColB + m) : 0.f;

        // ---- load h k-slice: 32 coalesced LDG.64, already packed ----
        {
            const ull* hp = g_hP + (size_t)kp0 * 32 + lane;
#pragma unroll
            for (int i = 0; i < 32; i++)
                v2[i] = __ldcg(hp + i * 32);
        }

        // ---- phase A: 16 cols (8 z + 8 r), this warp's 64 k ----
#pragma unroll 2
        for (int c = 0; c < 16; c++) {
            const ulonglong2* wp = (const ulonglong2*)(ws + c * 512 + kp0);
            ull a0 = 0, a1 = 0;
#pragma unroll
            for (int i = 0; i < 16; i++) {
                ulonglong2 u = wp[i];
                a0 = ffma2(v2[2*i],   u.x, a0);
                a1 = ffma2(v2[2*i+1], u.y, a1);
            }
            a0 = fadd2(a0, a1);
            float x, y; upk2(a0, x, y);
            red[(c * 32 + lane) * 17 + w] = x + y;
        }
        __syncthreads();

        // ---- reduce + gate epilogue: thread (c=w, b=lane) ----
        {
            const float* rp = red + (w * 32 + lane) * 17;
            float sum = xpA;
#pragma unroll
            for (int t = 0; t < 16; t++) sum += rp[t];
            float sg = 1.f / (1.f + expf(-sum));
            if (w < 8) {
                s_z[lane * 8 + w] = sg;
            } else {
                int c = w - 8;
                int j = j0 + c;
                rhPf[(j >> 1) * 64 + lane * 2 + (j & 1)] = sg * s_h[lane * 8 + c];
            }
        }
        grid_barrier();

        // ---- load rh k-slice (reuses v2) ----
        {
            const ull* rp8 = g_rhP + (size_t)kp0 * 32 + lane;
#pragma unroll
            for (int i = 0; i < 32; i++)
                v2[i] = __ldcg(rp8 + i * 32);
        }

        // ---- phase B: 8 g cols ----
#pragma unroll 2
        for (int c = 0; c < 8; c++) {
            const ulonglong2* wp = (const ulonglong2*)(ws + (16 + c) * 512 + kp0);
            ull a0 = 0, a1 = 0;
#pragma unroll
            for (int i = 0; i < 16; i++) {
                ulonglong2 u = wp[i];
                a0 = ffma2(v2[2*i],   u.x, a0);
                a1 = ffma2(v2[2*i+1], u.y, a1);
            }
            a0 = fadd2(a0, a1);
            float x, y; upk2(a0, x, y);
            red[(c * 32 + lane) * 17 + w] = x + y;
        }
        __syncthreads();

        // ---- reduce + h update: thread (c=w<8, b=lane) ----
        if (w < 8) {
            const float* rp = red + (w * 32 + lane) * 17;
            float sum = xpB;
#pragma unroll
            for (int t = 0; t < 16; t++) sum += rp[t];
            float gg = tanhf(sum);
            float zz = s_z[lane * 8 + w];
            float ho = s_h[lane * 8 + w];
            float hn = zz * ho + (1.f - zz) * gg;
            int j = j0 + w;
            s_h[lane * 8 + w] = hn;
            hPf[(j >> 1) * 64 + lane * 2 + (j & 1)] = hn;
            hs[(size_t)(s * B_ + lane) * H_ + j] = hn;
            if (s == S_ - 1) hlast[(size_t)(lane * L_ + layer) * H_ + j] = hn;
        }
        grid_barrier();
    }
}

// ---------------- host launch ----------------
extern "C" void kernel_launch(void* const* d_in, const int* in_sizes, int n_in,
                              void* d_out, int out_size)
{
    const float* x    = (const float*)d_in[0];
    const float* h0   = (const float*)d_in[1];
    const float* Wx0  = (const float*)d_in[2];
    const float* Wh0  = (const float*)d_in[3];
    const float* bh0  = (const float*)d_in[4];
    const float* Wx   = (const float*)d_in[5];
    const float* Wh   = (const float*)d_in[6];
    const float* bh   = (const float*)d_in[7];
    const float* Wout = (const float*)d_in[8];
    const float* bout = (const float*)d_in[9];

    float* out = (float*)d_out;
    float* hid = out + (size_t)B_ * S_ * O_;

    float *p_xT, *p_xpT, *p_hs;
    cudaGetSymbolAddress((void**)&p_xT, g_xT);
    cudaGetSymbolAddress((void**)&p_xpT, g_xpT);
    cudaGetSymbolAddress((void**)&p_hs, g_hs);

    const int rec_smem = 24576 * 4 + 16 * 32 * 17 * 4;   // 98304 + 34816 = 133120
    cudaFuncSetAttribute(gru_rec_kernel,
                         cudaFuncAttributeMaxDynamicSharedMemorySize, rec_smem);

    // 1) transpose x -> [s*B+b][i]
    transpose_kernel<<<4096, 256>>>((const float4*)x, (float4*)p_xT);

    // 2) layer 0
    gemm_kernel<<<dim3(G3H / 128, M_TOT / 128), 256>>>(p_xT, Wx0, bh0, p_xpT, I_, G3H, 0);
    gru_rec_kernel<<<NCTA_REC, 512, rec_smem>>>(Wh0, p_xpT, p_hs, h0, 0, hid);

    // 3) layer 1
    gemm_kernel<<<dim3(G3H / 128, M_TOT / 128), 256>>>(p_hs, Wx, bh, p_xpT, H_, G3H, 0);
    gru_rec_kernel<<<NCTA_REC, 512, rec_smem>>>(Wh, p_xpT, p_hs, h0, 1, hid);

    // 4) layer 2
    gemm_kernel<<<dim3(G3H / 128, M_TOT / 128), 256>>>(
        p_hs, Wx + (size_t)3 * H_ * H_, bh + 3 * H_, p_xpT, H_, G3H, 0);
    gru_rec_kernel<<<NCTA_REC, 512, rec_smem>>>(
        Wh + (size_t)3 * H_ * H_, p_xpT, p_hs, h0, 2, hid);

    // 5) output head -> d_out [B,S,O]
    gemm_kernel<<<dim3(O_ / 128, M_TOT / 128), 256>>>(p_hs, Wout, bout, out, H_, O_, 1);
}

// round 13
// speedup vs baseline: 1.6083x; 1.0374x over previous
#include <cuda_runtime.h>
#include <math.h>

#define B_  32
#define S_  512
#define I_  256
#define H_  1024
#define O_  256
#define L_  3
#define G3H (3*H_)
#define M_TOT (S_*B_)
#define NCTA_REC 128

typedef unsigned long long ull;

// ---------------- f32x2 packed math (sm_103a FFMA2 path) ----------------
__device__ __forceinline__ ull pk2(float x, float y) {
    ull r;
    asm("mov.b64 %0, {%1, %2};" : "=l"(r)
        : "r"(__float_as_uint(x)), "r"(__float_as_uint(y)));
    return r;
}
__device__ __forceinline__ void upk2(ull p, float& x, float& y) {
    unsigned int a, b;
    asm("mov.b64 {%0, %1}, %2;" : "=r"(a), "=r"(b) : "l"(p));
    x = __uint_as_float(a); y = __uint_as_float(b);
}
__device__ __forceinline__ ull ffma2(ull a, ull b, ull c) {
    ull d;
    asm("fma.rn.f32x2 %0, %1, %2, %3;" : "=l"(d) : "l"(a), "l"(b), "l"(c));
    return d;
}
__device__ __forceinline__ ull fadd2(ull a, ull b) {
    ull d;
    asm("add.rn.f32x2 %0, %1, %2;" : "=l"(d) : "l"(a), "l"(b));
    return d;
}

// ---------------- device scratch (allocation-free) ----------------
__device__ float g_xT[(size_t)M_TOT*I_];        // 16 MB  transposed x -> [s*B+b][i]
__device__ float g_xpT[(size_t)G3H*M_TOT];      // 201 MB xproj TRANSPOSED [col][s*B+b]
__device__ float g_hs[(size_t)M_TOT*H_];        // 64 MB  layer output sequence [s*B+b][h]
__device__ ull   g_hP [(H_/2)*B_];              // hidden, [kpair][b] packed f32x2
__device__ ull   g_rhP[(H_/2)*B_];              // r*h,    [kpair][b] packed f32x2
__device__ unsigned int g_barcount;
__device__ unsigned int g_bargen;

// ---------------- grid-wide barrier (PROVEN atomic version — do not touch) ----------------
__device__ __forceinline__ void grid_barrier()
{
    __syncthreads();
    if (threadIdx.x == 0) {
        unsigned int gen = *(volatile unsigned int*)&g_bargen;
        __threadfence();
        if (atomicAdd(&g_barcount, 1u) == gridDim.x - 1u) {
            g_barcount = 0u;
            __threadfence();
            atomicAdd(&g_bargen, 1u);
        } else {
            while (*(volatile unsigned int*)&g_bargen == gen) { __nanosleep(32); }
        }
        __threadfence();
    }
    __syncthreads();
}

// ---------------- transpose x[b][s][i] -> xT[(s*B+b)][i] ----------------
__global__ void transpose_kernel(const float4* __restrict__ x, float4* __restrict__ xT)
{
    int idx = blockIdx.x * blockDim.x + threadIdx.x;   // over S*B*I/4
    int i4 = idx & 63;          // I/4 = 64
    int m  = idx >> 6;          // m = s*B + b
    int b  = m & 31;
    int s  = m >> 5;
    xT[idx] = x[(size_t)(b * S_ + s) * 64 + i4];
}

// ---------------- SGEMM: C = A*W^T + bias, double-buffered smem ----------------
// mode 0: write TRANSPOSED  C_T[n][m]   (xproj -> g_xpT)
// mode 1: m=(s*B+b) -> C[(b*S+s)*O + n] (final output head)
__global__ void __launch_bounds__(256) gemm_kernel(
    const float* __restrict__ A, const float* __restrict__ W,
    const float* __restrict__ bias, float* __restrict__ C,
    int K, int N, int mode)
{
    __shared__ float As[2][16][128];
    __shared__ float Bs[2][16][128];

    const int tid  = threadIdx.x;
    const int bx   = blockIdx.x;   // N tile
    const int by   = blockIdx.y;   // M tile
    const int lrow = tid >> 1;
    const int lc4  = (tid & 1) << 2;

    const float* Arow = A + (size_t)(by * 128 + lrow) * K + lc4;
    const float* Wrow = W + (size_t)(bx * 128 + lrow) * K + lc4;

    const int tx = tid & 15;
    const int ty = tid >> 4;

    ull acc2[8][4];
#pragma unroll
    for (int i = 0; i < 8; i++)
#pragma unroll
        for (int j = 0; j < 4; j++) acc2[i][j] = 0ull;

    // prologue: tile 0 -> buf 0
    {
        float4 a0 = *(const float4*)(Arow);
        float4 a1 = *(const float4*)(Arow + 8);
        float4 w0 = *(const float4*)(Wrow);
        float4 w1 = *(const float4*)(Wrow + 8);
        As[0][lc4 + 0][lrow] = a0.x; As[0][lc4 + 1][lrow] = a0.y;
        As[0][lc4 + 2][lrow] = a0.z; As[0][lc4 + 3][lrow] = a0.w;
        As[0][lc4 + 8][lrow] = a1.x; As[0][lc4 + 9][lrow] = a1.y;
        As[0][lc4 +10][lrow] = a1.z; As[0][lc4 +11][lrow] = a1.w;
        Bs[0][lc4 + 0][lrow] = w0.x; Bs[0][lc4 + 1][lrow] = w0.y;
        Bs[0][lc4 + 2][lrow] = w0.z; Bs[0][lc4 + 3][lrow] = w0.w;
        Bs[0][lc4 + 8][lrow] = w1.x; Bs[0][lc4 + 9][lrow] = w1.y;
        Bs[0][lc4 +10][lrow] = w1.z; Bs[0][lc4 +11][lrow] = w1.w;
    }
    __syncthreads();

    int p = 0;
    for (int kt = 0; kt < K; kt += 16) {
        const bool nxt = (kt + 16) < K;
        float4 a0, a1, w0, w1;
        if (nxt) {                               // issue next-tile loads early
            a0 = *(const float4*)(Arow + kt + 16);
            a1 = *(const float4*)(Arow + kt + 24);
            w0 = *(const float4*)(Wrow + kt + 16);
            w1 = *(const float4*)(Wrow + kt + 24);
        }
#pragma unroll
        for (int k = 0; k < 16; k++) {
            float4 av0 = *(const float4*)&As[p][k][ty * 8];
            float4 av1 = *(const float4*)&As[p][k][ty * 8 + 4];
            // b-operands come out of smem ALREADY packed as f32x2 pairs
            ulonglong2 b01 = *(const ulonglong2*)&Bs[p][k][tx * 8];
            ulonglong2 b23 = *(const ulonglong2*)&Bs[p][k][tx * 8 + 4];
            ull pb0 = b01.x, pb1 = b01.y, pb2 = b23.x, pb3 = b23.y;
            float a_[8] = {av0.x, av0.y, av0.z, av0.w, av1.x, av1.y, av1.z, av1.w};
#pragma unroll
            for (int i = 0; i < 8; i++) {
                ull pa = pk2(a_[i], a_[i]);
                acc2[i][0] = ffma2(pa, pb0, acc2[i][0]);
                acc2[i][1] = ffma2(pa, pb1, acc2[i][1]);
                acc2[i][2] = ffma2(pa, pb2, acc2[i][2]);
                acc2[i][3] = ffma2(pa, pb3, acc2[i][3]);
            }
        }
        if (nxt) {
            const int q = p ^ 1;
            As[q][lc4 + 0][lrow] = a0.x; As[q][lc4 + 1][lrow] = a0.y;
            As[q][lc4 + 2][lrow] = a0.z; As[q][lc4 + 3][lrow] = a0.w;
            As[q][lc4 + 8][lrow] = a1.x; As[q][lc4 + 9][lrow] = a1.y;
            As[q][lc4 +10][lrow] = a1.z; As[q][lc4 +11][lrow] = a1.w;
            Bs[q][lc4 + 0][lrow] = w0.x; Bs[q][lc4 + 1][lrow] = w0.y;
            Bs[q][lc4 + 2][lrow] = w0.z; Bs[q][lc4 + 3][lrow] = w0.w;
            Bs[q][lc4 + 8][lrow] = w1.x; Bs[q][lc4 + 9][lrow] = w1.y;
            Bs[q][lc4 +10][lrow] = w1.z; Bs[q][lc4 +11][lrow] = w1.w;
            __syncthreads();
            p = q;
        }
    }

    const int mbase = by * 128 + ty * 8;
    const int nbase = bx * 128 + tx * 8;
    float bb[8];
#pragma unroll
    for (int j = 0; j < 8; j++) bb[j] = bias[nbase + j];

#pragma unroll
    for (int i = 0; i < 8; i++) {
        int m = mbase + i;
        float cv[8];
#pragma unroll
        for (int j = 0; j < 4; j++) upk2(acc2[i][j], cv[2*j], cv[2*j+1]);
#pragma unroll
        for (int j = 0; j < 8; j++) {
            float v = cv[j] + bb[j];
            if (mode == 0) {
                C[(size_t)(nbase + j) * M_TOT + m] = v;      // transposed
            } else {
                int b = m & 31, s = m >> 5;
                C[(size_t)((b << 9) + s) * O_ + (nbase + j)] = v;
            }
        }
    }
}

// ---------------- persistent GRU recurrence (one layer) ----------------
// 128 CTAs (1/SM, co-resident), 512 threads = 16 warps.
// CTA owns gate columns [cta*8, cta*8+8) of z, r, g.
// Warp w = k-slice [w*64, w*64+64). lane = batch b.
// h/r*h in [kpair][b] packed layout (coalesced LDG.64, pre-packed for FFMA2).
// xp in TRANSPOSED [col][m] layout -> epilogue fetches are coalesced too.
__global__ void __launch_bounds__(512, 1) gru_rec_kernel(
    const float* __restrict__ Wh,      // [3H][H]
    const float* __restrict__ xpT,     // [3H][S*B] (bias folded in)
    float*       __restrict__ hs,      // [S*B][H]
    const float* __restrict__ h0,      // [B][L][H]
    int layer,
    float*       __restrict__ hlast)   // d_out + B*S*O : [B][L][H]
{
    extern __shared__ float sh[];
    ull*   ws  = (ull*)sh;             // [24 cols][512 k-pairs]   96 KB
    float* red = sh + 24576;           // [16][32][17] partials    34 KB
    __shared__ float s_z[B_ * 8];      // z values   [b][c]
    __shared__ float s_h[B_ * 8];      // h (own 8 cols) [b][c]

    const int tid  = threadIdx.x;
    const int cta  = blockIdx.x;
    const int w    = tid >> 5;         // 0..15 : k-slice AND epilogue column
    const int lane = tid & 31;         // batch b
    const int j0   = cta * 8;
    const int kp0  = w * 32;           // base k-pair of this warp's slice

    float* hPf  = (float*)g_hP;
    float* rhPf = (float*)g_rhP;

    // ---- preload this CTA's 24 weight rows, packed k-pairs ----
    for (int rr = w; rr < 24; rr += 16) {
        int row = (rr < 8)  ? (j0 + rr)
                : (rr < 16) ? (H_ + j0 + (rr - 8))
                            : (2 * H_ + j0 + (rr - 16));
        const float2* src = (const float2*)(Wh + (size_t)row * H_);
        for (int i = lane; i < 512; i += 32) {
            float2 v = __ldg(src + i);
            ws[rr * 512 + i] = pk2(v.x, v.y);
        }
    }

    // ---- init hidden state: g_hP[(j>>1)*64 + b*2 + (j&1)] (as floats) ----
    {
        int i = cta * 512 + tid;
        if (i < B_ * H_) {
            int b = i >> 10, j = i & 1023;
            hPf[(j >> 1) * 64 + b * 2 + (j & 1)] = h0[(b * L_ + layer) * H_ + j];
        }
        if (w < 8) s_h[lane * 8 + w] = h0[(lane * L_ + layer) * H_ + j0 + w];
    }
    grid_barrier();

    // per-thread xp column bases (coalesced: lane-consecutive m)
    const float* xpColA = xpT + (size_t)((w < 8) ? (j0 + w) : (H_ + j0 + (w - 8))) * M_TOT;
    const float* xpColB = (w < 8) ? (xpT + (size_t)(2 * H_ + j0 + w) * M_TOT) : xpT;

    ull v2[32];                        // operand regs, reused between phases

    for (int s = 0; s < S_; s++) {
        // ---- prefetch xp for this thread's epilogue column (coalesced) ----
        const int m = s * B_ + lane;
        float xpA = __ldg(xpColA + m);
        float xpB = (w < 8) ? __ldg(xpColB + m) : 0.f;

        // ---- load h k-slice: 32 coalesced LDG.64, already packed ----
        {
            const ull* hp = g_hP + (size_t)kp0 * 32 + lane;
#pragma unroll
            for (int i = 0; i < 32; i++)
                v2[i] = __ldcg(hp + i * 32);
        }

        // ---- phase A: 16 cols (8 z + 8 r), this warp's 64 k ----
#pragma unroll 2
        for (int c = 0; c < 16; c++) {
            const ulonglong2* wp = (const ulonglong2*)(ws + c * 512 + kp0);
            ull a0 = 0, a1 = 0;
#pragma unroll
            for (int i = 0; i < 16; i++) {
                ulonglong2 u = wp[i];
                a0 = ffma2(v2[2*i],   u.x, a0);
                a1 = ffma2(v2[2*i+1], u.y, a1);
            }
            a0 = fadd2(a0, a1);
            float x, y; upk2(a0, x, y);
            red[(c * 32 + lane) * 17 + w] = x + y;
        }
        __syncthreads();

        // ---- reduce + gate epilogue: thread (c=w, b=lane) ----
        {
            const float* rp = red + (w * 32 + lane) * 17;
            float sum = xpA;
#pragma unroll
            for (int t = 0; t < 16; t++) sum += rp[t];
            float sg = 1.f / (1.f + expf(-sum));
            if (w < 8) {
                s_z[lane * 8 + w] = sg;
            } else {
                int c = w - 8;
                int j = j0 + c;
                rhPf[(j >> 1) * 64 + lane * 2 + (j & 1)] = sg * s_h[lane * 8 + c];
            }
        }
        grid_barrier();

        // ---- load rh k-slice (reuses v2) ----
        {
            const ull* rp8 = g_rhP + (size_t)kp0 * 32 + lane;
#pragma unroll
            for (int i = 0; i < 32; i++)
                v2[i] = __ldcg(rp8 + i * 32);
        }

        // ---- phase B: 8 g cols ----
#pragma unroll 2
        for (int c = 0; c < 8; c++) {
            const ulonglong2* wp = (const ulonglong2*)(ws + (16 + c) * 512 + kp0);
            ull a0 = 0, a1 = 0;
#pragma unroll
            for (int i = 0; i < 16; i++) {
                ulonglong2 u = wp[i];
                a0 = ffma2(v2[2*i],   u.x, a0);
                a1 = ffma2(v2[2*i+1], u.y, a1);
            }
            a0 = fadd2(a0, a1);
            float x, y; upk2(a0, x, y);
            red[(c * 32 + lane) * 17 + w] = x + y;
        }
        __syncthreads();

        // ---- reduce + h update: thread (c=w<8, b=lane) ----
        if (w < 8) {
            const float* rp = red + (w * 32 + lane) * 17;
            float sum = xpB;
#pragma unroll
            for (int t = 0; t < 16; t++) sum += rp[t];
            float gg = tanhf(sum);
            float zz = s_z[lane * 8 + w];
            float ho = s_h[lane * 8 + w];
            float hn = zz * ho + (1.f - zz) * gg;
            int j = j0 + w;
            s_h[lane * 8 + w] = hn;
            hPf[(j >> 1) * 64 + lane * 2 + (j & 1)] = hn;
            hs[(size_t)(s * B_ + lane) * H_ + j] = hn;
            if (s == S_ - 1) hlast[(size_t)(lane * L_ + layer) * H_ + j] = hn;
        }
        grid_barrier();
    }
}

// ---------------- host launch ----------------
extern "C" void kernel_launch(void* const* d_in, const int* in_sizes, int n_in,
                              void* d_out, int out_size)
{
    const float* x    = (const float*)d_in[0];
    const float* h0   = (const float*)d_in[1];
    const float* Wx0  = (const float*)d_in[2];
    const float* Wh0  = (const float*)d_in[3];
    const float* bh0  = (const float*)d_in[4];
    const float* Wx   = (const float*)d_in[5];
    const float* Wh   = (const float*)d_in[6];
    const float* bh   = (const float*)d_in[7];
    const float* Wout = (const float*)d_in[8];
    const float* bout = (const float*)d_in[9];

    float* out = (float*)d_out;
    float* hid = out + (size_t)B_ * S_ * O_;

    float *p_xT, *p_xpT, *p_hs;
    cudaGetSymbolAddress((void**)&p_xT, g_xT);
    cudaGetSymbolAddress((void**)&p_xpT, g_xpT);
    cudaGetSymbolAddress((void**)&p_hs, g_hs);

    const int rec_smem = 24576 * 4 + 16 * 32 * 17 * 4;   // 98304 + 34816 = 133120
    cudaFuncSetAttribute(gru_rec_kernel,
                         cudaFuncAttributeMaxDynamicSharedMemorySize, rec_smem);

    // 1) transpose x -> [s*B+b][i]
    transpose_kernel<<<4096, 256>>>((const float4*)x, (float4*)p_xT);

    // 2) layer 0
    gemm_kernel<<<dim3(G3H / 128, M_TOT / 128), 256>>>(p_xT, Wx0, bh0, p_xpT, I_, G3H, 0);
    gru_rec_kernel<<<NCTA_REC, 512, rec_smem>>>(Wh0, p_xpT, p_hs, h0, 0, hid);

    // 3) layer 1
    gemm_kernel<<<dim3(G3H / 128, M_TOT / 128), 256>>>(p_hs, Wx, bh, p_xpT, H_, G3H, 0);
    gru_rec_kernel<<<NCTA_REC, 512, rec_smem>>>(Wh, p_xpT, p_hs, h0, 1, hid);

    // 4) layer 2
    gemm_kernel<<<dim3(G3H / 128, M_TOT / 128), 256>>>(
        p_hs, Wx + (size_t)3 * H_ * H_, bh + 3 * H_, p_xpT, H_, G3H, 0);
    gru_rec_kernel<<<NCTA_REC, 512, rec_smem>>>(
        Wh + (size_t)3 * H_ * H_, p_xpT, p_hs, h0, 2, hid);

    // 5) output head -> d_out [B,S,O]
    gemm_kernel<<<dim3(O_ / 128, M_TOT / 128), 256>>>(p_hs, Wout, bout, out, H_, O_, 1);
}

// round 16
// speedup vs baseline: 1.7992x; 1.1187x over previous
#include <cuda_runtime.h>
#include <cuda_bf16.h>
#include <cstdint>
#include <math.h>

#define B_  32
#define S_  512
#define I_  256
#define H_  1024
#define O_  256
#define L_  3
#define G3H (3*H_)
#define M_TOT (S_*B_)
#define NCTA_REC 128

typedef unsigned long long ull;

// ---------------- f32x2 packed math (sm_103a FFMA2 path) ----------------
__device__ __forceinline__ ull pk2(float x, float y) {
    ull r;
    asm("mov.b64 %0, {%1, %2};" : "=l"(r)
        : "r"(__float_as_uint(x)), "r"(__float_as_uint(y)));
    return r;
}
__device__ __forceinline__ void upk2(ull p, float& x, float& y) {
    unsigned int a, b;
    asm("mov.b64 {%0, %1}, %2;" : "=r"(a), "=r"(b) : "l"(p));
    x = __uint_as_float(a); y = __uint_as_float(b);
}
__device__ __forceinline__ ull ffma2(ull a, ull b, ull c) {
    ull d;
    asm("fma.rn.f32x2 %0, %1, %2, %3;" : "=l"(d) : "l"(a), "l"(b), "l"(c));
    return d;
}
__device__ __forceinline__ ull fadd2(ull a, ull b) {
    ull d;
    asm("add.rn.f32x2 %0, %1, %2;" : "=l"(d) : "l"(a), "l"(b));
    return d;
}

// ---------------- warp MMA: m16n8k16 bf16 (baseline PTX, sm_80+) ----------------
__device__ __forceinline__ void mma16816(float* c, const uint32_t* a, const uint32_t* b)
{
    asm volatile(
        "mma.sync.aligned.m16n8k16.row.col.f32.bf16.bf16.f32 "
        "{%0,%1,%2,%3}, {%4,%5,%6,%7}, {%8,%9}, {%0,%1,%2,%3};"
        : "+f"(c[0]), "+f"(c[1]), "+f"(c[2]), "+f"(c[3])
        : "r"(a[0]), "r"(a[1]), "r"(a[2]), "r"(a[3]), "r"(b[0]), "r"(b[1]));
}

// ---------------- device scratch (allocation-free) ----------------
__device__ float g_xT[(size_t)M_TOT*I_];        // 16 MB  transposed x -> [s*B+b][i]
__device__ float g_xpT[(size_t)G3H*M_TOT];      // 201 MB xproj TRANSPOSED [col][s*B+b]
__device__ float g_hs[(size_t)M_TOT*H_];        // 64 MB  layer output sequence [s*B+b][h]
__device__ ull   g_hP [(H_/2)*B_];              // hidden, [kpair][b] packed f32x2
__device__ ull   g_rhP[(H_/2)*B_];              // r*h,    [kpair][b] packed f32x2
__device__ __nv_bfloat16 g_A0[(size_t)M_TOT*H_];  // A split hi
__device__ __nv_bfloat16 g_A1[(size_t)M_TOT*H_];  // A split lo
__device__ __nv_bfloat16 g_W0[(size_t)G3H*H_];    // W split hi
__device__ __nv_bfloat16 g_W1[(size_t)G3H*H_];    // W split lo
__device__ unsigned int g_barcount;
__device__ unsigned int g_bargen;

// ---------------- grid-wide barrier (PROVEN atomic version — do not touch) ----------------
__device__ __forceinline__ void grid_barrier()
{
    __syncthreads();
    if (threadIdx.x == 0) {
        unsigned int gen = *(volatile unsigned int*)&g_bargen;
        __threadfence();
        if (atomicAdd(&g_barcount, 1u) == gridDim.x - 1u) {
            g_barcount = 0u;
            __threadfence();
            atomicAdd(&g_bargen, 1u);
        } else {
            while (*(volatile unsigned int*)&g_bargen == gen) { __nanosleep(32); }
        }
        __threadfence();
    }
    __syncthreads();
}

// ---------------- transpose x[b][s][i] -> xT[(s*B+b)][i] ----------------
__global__ void transpose_kernel(const float4* __restrict__ x, float4* __restrict__ xT)
{
    int idx = blockIdx.x * blockDim.x + threadIdx.x;   // over S*B*I/4
    int i4 = idx & 63;          // I/4 = 64
    int m  = idx >> 6;          // m = s*B + b
    int b  = m & 31;
    int s  = m >> 5;
    xT[idx] = x[(size_t)(b * S_ + s) * 64 + i4];
}

// ---------------- bf16 two-component split: x = d0 + d1 + O(2^-17 x) ----------------
__global__ void split_kernel(const float* __restrict__ src,
                             __nv_bfloat16* __restrict__ d0,
                             __nv_bfloat16* __restrict__ d1, int n)
{
    int i = blockIdx.x * blockDim.x + threadIdx.x;
    if (i < n) {
        float x = src[i];
        __nv_bfloat16 b0 = __float2bfloat16(x);
        float r = x - __bfloat162float(b0);
        d0[i] = b0;
        d1[i] = __float2bfloat16(r);
    }
}

// ---------------- tensor-core GEMM via mma.sync bf16-split (3 MMA per product) ----
// C[m][n] = sum_k A[m][k]*W[n][k] + bias[n], computed as A0W0 + A0W1 + A1W0.
// Tile 128x128, 256 threads = 8 warps (2m x 4n), warp tile 64x32, BLOCK_K=32.
// smem row stride 40 bf16 -> conflict-free fragment LDS (banks r*20+t distinct).
// mode 0: write TRANSPOSED  C_T[n][m]   (xproj -> g_xpT)
// mode 1: m=(s*B+b) -> C[((b<<9)+s)*O + n] (final output head)
__global__ void __launch_bounds__(256) gemm_mma_kernel(
    const __nv_bfloat16* __restrict__ A0, const __nv_bfloat16* __restrict__ A1,
    const __nv_bfloat16* __restrict__ W0, const __nv_bfloat16* __restrict__ W1,
    const float* __restrict__ bias, float* __restrict__ C,
    int K, int mode)
{
    __shared__ __nv_bfloat16 sA0[128][40];
    __shared__ __nv_bfloat16 sA1[128][40];
    __shared__ __nv_bfloat16 sW0[128][40];
    __shared__ __nv_bfloat16 sW1[128][40];

    const int tid  = threadIdx.x;
    const int wid  = tid >> 5;
    const int lane = tid & 31;
    const int wm   = wid >> 2;          // 0..1
    const int wn   = wid & 3;           // 0..3
    const int g    = lane >> 2;         // 0..7
    const int t    = lane & 3;          // 0..3
    const int mbase = blockIdx.y * 128;
    const int nbase = blockIdx.x * 128;

    float c[4][4][4];
#pragma unroll
    for (int mi = 0; mi < 4; mi++)
#pragma unroll
        for (int ni = 0; ni < 4; ni++)
#pragma unroll
            for (int f = 0; f < 4; f++) c[mi][ni][f] = 0.f;

    for (int kt = 0; kt < K; kt += 32) {
        __syncthreads();
        // ---- stage k-tile: 4 arrays x 128 rows x 32 cols, uint2 (4 bf16) vectors ----
#pragma unroll
        for (int i = 0; i < 4; i++) {
            int v   = tid + i * 256;    // 0..1023
            int row = v >> 3;
            int cv  = v & 7;
            size_t goff = (size_t)(mbase + row) * K + kt + cv * 4;
            size_t woff = (size_t)(nbase + row) * K + kt + cv * 4;
            *(uint2*)&sA0[row][cv * 4] = *(const uint2*)(A0 + goff);
            *(uint2*)&sA1[row][cv * 4] = *(const uint2*)(A1 + goff);
            *(uint2*)&sW0[row][cv * 4] = *(const uint2*)(W0 + woff);
            *(uint2*)&sW1[row][cv * 4] = *(const uint2*)(W1 + woff);
        }
        __syncthreads();

#pragma unroll
        for (int ks = 0; ks < 2; ks++) {
            const int kk = ks * 16 + t * 2;
            // B fragments for this warp's 4 n-subtiles
            uint32_t w0f[4][2], w1f[4][2];
#pragma unroll
            for (int ni = 0; ni < 4; ni++) {
                int nr = wn * 32 + ni * 8 + g;
                w0f[ni][0] = *(const uint32_t*)&sW0[nr][kk];
                w0f[ni][1] = *(const uint32_t*)&sW0[nr][kk + 8];
                w1f[ni][0] = *(const uint32_t*)&sW1[nr][kk];
                w1f[ni][1] = *(const uint32_t*)&sW1[nr][kk + 8];
            }
#pragma unroll
            for (int mi = 0; mi < 4; mi++) {
                int mr = wm * 64 + mi * 16 + g;
                uint32_t a0f[4], a1f[4];
                a0f[0] = *(const uint32_t*)&sA0[mr][kk];
                a0f[1] = *(const uint32_t*)&sA0[mr + 8][kk];
                a0f[2] = *(const uint32_t*)&sA0[mr][kk + 8];
                a0f[3] = *(const uint32_t*)&sA0[mr + 8][kk + 8];
                a1f[0] = *(const uint32_t*)&sA1[mr][kk];
                a1f[1] = *(const uint32_t*)&sA1[mr + 8][kk];
                a1f[2] = *(const uint32_t*)&sA1[mr][kk + 8];
                a1f[3] = *(const uint32_t*)&sA1[mr + 8][kk + 8];
#pragma unroll
                for (int ni = 0; ni < 4; ni++) {
                    mma16816(c[mi][ni], a0f, w0f[ni]);
                    mma16816(c[mi][ni], a0f, w1f[ni]);
                    mma16816(c[mi][ni], a1f, w0f[ni]);
                }
            }
        }
    }

    // ---- epilogue ----
#pragma unroll
    for (int mi = 0; mi < 4; mi++) {
#pragma unroll
        for (int ni = 0; ni < 4; ni++) {
            int mr = mbase + wm * 64 + mi * 16 + g;
            int nc = nbase + wn * 32 + ni * 8 + t * 2;
            float b0v = __ldg(&bias[nc]);
            float b1v = __ldg(&bias[nc + 1]);
            if (mode == 0) {
                C[(size_t)nc * M_TOT + mr]           = c[mi][ni][0] + b0v;
                C[(size_t)(nc + 1) * M_TOT + mr]     = c[mi][ni][1] + b1v;
                C[(size_t)nc * M_TOT + mr + 8]       = c[mi][ni][2] + b0v;
                C[(size_t)(nc + 1) * M_TOT + mr + 8] = c[mi][ni][3] + b1v;
            } else {
                int b0i = mr & 31, s0 = mr >> 5;
                int b1i = (mr + 8) & 31, s1 = (mr + 8) >> 5;
                float* d0 = C + (size_t)((b0i << 9) + s0) * O_;
                float* d1 = C + (size_t)((b1i << 9) + s1) * O_;
                d0[nc]     = c[mi][ni][0] + b0v;
                d0[nc + 1] = c[mi][ni][1] + b1v;
                d1[nc]     = c[mi][ni][2] + b0v;
                d1[nc + 1] = c[mi][ni][3] + b1v;
            }
        }
    }
}

// ---------------- persistent GRU recurrence (one layer) — PROVEN, unchanged ----------------
__global__ void __launch_bounds__(512, 1) gru_rec_kernel(
    const float* __restrict__ Wh,      // [3H][H]
    const float* __restrict__ xpT,     // [3H][S*B] (bias folded in)
    float*       __restrict__ hs,      // [S*B][H]
    const float* __restrict__ h0,      // [B][L][H]
    int layer,
    float*       __restrict__ hlast)   // d_out + B*S*O : [B][L][H]
{
    extern __shared__ float sh[];
    ull*   ws  = (ull*)sh;             // [24 cols][512 k-pairs]   96 KB
    float* red = sh + 24576;           // [16][32][17] partials    34 KB
    __shared__ float s_z[B_ * 8];      // z values   [b][c]
    __shared__ float s_h[B_ * 8];      // h (own 8 cols) [b][c]

    const int tid  = threadIdx.x;
    const int cta  = blockIdx.x;
    const int w    = tid >> 5;         // 0..15 : k-slice AND epilogue column
    const int lane = tid & 31;         // batch b
    const int j0   = cta * 8;
    const int kp0  = w * 32;           // base k-pair of this warp's slice

    float* hPf  = (float*)g_hP;
    float* rhPf = (float*)g_rhP;

    // ---- preload this CTA's 24 weight rows, packed k-pairs ----
    for (int rr = w; rr < 24; rr += 16) {
        int row = (rr < 8)  ? (j0 + rr)
                : (rr < 16) ? (H_ + j0 + (rr - 8))
                            : (2 * H_ + j0 + (rr - 16));
        const float2* src = (const float2*)(Wh + (size_t)row * H_);
        for (int i = lane; i < 512; i += 32) {
            float2 v = __ldg(src + i);
            ws[rr * 512 + i] = pk2(v.x, v.y);
        }
    }

    // ---- init hidden state: g_hP[(j>>1)*64 + b*2 + (j&1)] (as floats) ----
    {
        int i = cta * 512 + tid;
        if (i < B_ * H_) {
            int b = i >> 10, j = i & 1023;
            hPf[(j >> 1) * 64 + b * 2 + (j & 1)] = h0[(b * L_ + layer) * H_ + j];
        }
        if (w < 8) s_h[lane * 8 + w] = h0[(lane * L_ + layer) * H_ + j0 + w];
    }
    grid_barrier();

    // per-thread xp column bases (coalesced: lane-consecutive m)
    const float* xpColA = xpT + (size_t)((w < 8) ? (j0 + w) : (H_ + j0 + (w - 8))) * M_TOT;
    const float* xpColB = (w < 8) ? (xpT + (size_t)(2 * H_ + j0 + w) * M_TOT) : xpT;

    ull v2[32];                        // operand regs, reused between phases

    for (int s = 0; s < S_; s++) {
        // ---- prefetch xp for this thread's epilogue column (coalesced) ----
        const int m = s * B_ + lane;
        float xpA = __ldg(xpColA + m);
        float xpB = (w < 8) ? __ldg(xpColB + m) : 0.f;

        // ---- load h k-slice: 32 coalesced LDG.64, already packed ----
        {
            const ull* hp = g_hP + (size_t)kp0 * 32 + lane;
#pragma unroll
            for (int i = 0; i < 32; i++)
                v2[i] = __ldcg(hp + i * 32);
        }

        // ---- phase A: 16 cols (8 z + 8 r), this warp's 64 k ----
#pragma unroll 2
        for (int c = 0; c < 16; c++) {
            const ulonglong2* wp = (const ulonglong2*)(ws + c * 512 + kp0);
            ull a0 = 0, a1 = 0;
#pragma unroll
            for (int i = 0; i < 16; i++) {
                ulonglong2 u = wp[i];
                a0 = ffma2(v2[2*i],   u.x, a0);
                a1 = ffma2(v2[2*i+1], u.y, a1);
            }
            a0 = fadd2(a0, a1);
            float x, y; upk2(a0, x, y);
            red[(c * 32 + lane) * 17 + w] = x + y;
        }
        __syncthreads();

        // ---- reduce + gate epilogue: thread (c=w, b=lane) ----
        {
            const float* rp = red + (w * 32 + lane) * 17;
            float sum = xpA;
#pragma unroll
            for (int tr = 0; tr < 16; tr++) sum += rp[tr];
            float sg = 1.f / (1.f + expf(-sum));
            if (w < 8) {
                s_z[lane * 8 + w] = sg;
            } else {
                int cc = w - 8;
                int j = j0 + cc;
                rhPf[(j >> 1) * 64 + lane * 2 + (j & 1)] = sg * s_h[lane * 8 + cc];
            }
        }
        grid_barrier();

        // ---- load rh k-slice (reuses v2) ----
        {
            const ull* rp8 = g_rhP + (size_t)kp0 * 32 + lane;
#pragma unroll
            for (int i = 0; i < 32; i++)
                v2[i] = __ldcg(rp8 + i * 32);
        }

        // ---- phase B: 8 g cols ----
#pragma unroll 2
        for (int c = 0; c < 8; c++) {
            const ulonglong2* wp = (const ulonglong2*)(ws + (16 + c) * 512 + kp0);
            ull a0 = 0, a1 = 0;
#pragma unroll
            for (int i = 0; i < 16; i++) {
                ulonglong2 u = wp[i];
                a0 = ffma2(v2[2*i],   u.x, a0);
                a1 = ffma2(v2[2*i+1], u.y, a1);
            }
            a0 = fadd2(a0, a1);
            float x, y; upk2(a0, x, y);
            red[(c * 32 + lane) * 17 + w] = x + y;
        }
        __syncthreads();

        // ---- reduce + h update: thread (c=w<8, b=lane) ----
        if (w < 8) {
            const float* rp = red + (w * 32 + lane) * 17;
            float sum = xpB;
#pragma unroll
            for (int tr = 0; tr < 16; tr++) sum += rp[tr];
            float gg = tanhf(sum);
            float zz = s_z[lane * 8 + w];
            float ho = s_h[lane * 8 + w];
            float hn = zz * ho + (1.f - zz) * gg;
            int j = j0 + w;
            s_h[lane * 8 + w] = hn;
            hPf[(j >> 1) * 64 + lane * 2 + (j & 1)] = hn;
            hs[(size_t)(s * B_ + lane) * H_ + j] = hn;
            if (s == S_ - 1) hlast[(size_t)(lane * L_ + layer) * H_ + j] = hn;
        }
        grid_barrier();
    }
}

// ---------------- host launch ----------------
extern "C" void kernel_launch(void* const* d_in, const int* in_sizes, int n_in,
                              void* d_out, int out_size)
{
    const float* x    = (const float*)d_in[0];
    const float* h0   = (const float*)d_in[1];
    const float* Wx0  = (const float*)d_in[2];
    const float* Wh0  = (const float*)d_in[3];
    const float* bh0  = (const float*)d_in[4];
    const float* Wx   = (const float*)d_in[5];
    const float* Wh   = (const float*)d_in[6];
    const float* bh   = (const float*)d_in[7];
    const float* Wout = (const float*)d_in[8];
    const float* bout = (const float*)d_in[9];

    float* out = (float*)d_out;
    float* hid = out + (size_t)B_ * S_ * O_;

    float *p_xT, *p_xpT, *p_hs;
    __nv_bfloat16 *p_A0, *p_A1, *p_W0, *p_W1;
    cudaGetSymbolAddress((void**)&p_xT, g_xT);
    cudaGetSymbolAddress((void**)&p_xpT, g_xpT);
    cudaGetSymbolAddress((void**)&p_hs, g_hs);
    cudaGetSymbolAddress((void**)&p_A0, g_A0);
    cudaGetSymbolAddress((void**)&p_A1, g_A1);
    cudaGetSymbolAddress((void**)&p_W0, g_W0);
    cudaGetSymbolAddress((void**)&p_W1, g_W1);

    const int rec_smem = 24576 * 4 + 16 * 32 * 17 * 4;   // 133120
    cudaFuncSetAttribute(gru_rec_kernel,
                         cudaFuncAttributeMaxDynamicSharedMemorySize, rec_smem);

    // 1) transpose x -> [s*B+b][i]
    transpose_kernel<<<4096, 256>>>((const float4*)x, (float4*)p_xT);

    // 2) layer 0: split A (K=256) + W, tensor GEMM, recurrence
    split_kernel<<<(M_TOT * I_ + 255) / 256, 256>>>(p_xT, p_A0, p_A1, M_TOT * I_);
    split_kernel<<<(G3H * I_ + 255) / 256, 256>>>(Wx0, p_W0, p_W1, G3H * I_);
    gemm_mma_kernel<<<dim3(G3H / 128, M_TOT / 128), 256>>>(
        p_A0, p_A1, p_W0, p_W1, bh0, p_xpT, I_, 0);
    gru_rec_kernel<<<NCTA_REC, 512, rec_smem>>>(Wh0, p_xpT, p_hs, h0, 0, hid);

    // 3) layer 1
    split_kernel<<<(M_TOT * H_ + 255) / 256, 256>>>(p_hs, p_A0, p_A1, M_TOT * H_);
    split_kernel<<<(G3H * H_ + 255) / 256, 256>>>(Wx, p_W0, p_W1, G3H * H_);
    gemm_mma_kernel<<<dim3(G3H / 128, M_TOT / 128), 256>>>(
        p_A0, p_A1, p_W0, p_W1, bh, p_xpT, H_, 0);
    gru_rec_kernel<<<NCTA_REC, 512, rec_smem>>>(Wh, p_xpT, p_hs, h0, 1, hid);

    // 4) layer 2
    split_kernel<<<(M_TOT * H_ + 255) / 256, 256>>>(p_hs, p_A0, p_A1, M_TOT * H_);
    split_kernel<<<(G3H * H_ + 255) / 256, 256>>>(Wx + (size_t)3 * H_ * H_, p_W0, p_W1, G3H * H_);
    gemm_mma_kernel<<<dim3(G3H / 128, M_TOT / 128), 256>>>(
        p_A0, p_A1, p_W0, p_W1, bh + 3 * H_, p_xpT, H_, 0);
    gru_rec_kernel<<<NCTA_REC, 512, rec_smem>>>(
        Wh + (size_t)3 * H_ * H_, p_xpT, p_hs, h0, 2, hid);

    // 5) output head -> d_out [B,S,O]
    split_kernel<<<(M_TOT * H_ + 255) / 256, 256>>>(p_hs, p_A0, p_A1, M_TOT * H_);
    split_kernel<<<(O_ * H_ + 255) / 256, 256>>>(Wout, p_W0, p_W1, O_ * H_);
    gemm_mma_kernel<<<dim3(O_ / 128, M_TOT / 128), 256>>>(
        p_A0, p_A1, p_W0, p_W1, bout, out, H_, 1);
}

// round 17
// speedup vs baseline: 2.4487x; 1.3610x over previous
#include <cuda_runtime.h>
#include <cuda_bf16.h>
#include <cstdint>
#include <math.h>

#define B_  32
#define S_  512
#define I_  256
#define H_  1024
#define O_  256
#define L_  3
#define G3H (3*H_)
#define M_TOT (S_*B_)
#define NCTA_REC 128

typedef unsigned long long ull;

// ---------------- f32x2 packed helpers (kept for GEMM-side compat) ----------------
__device__ __forceinline__ ull pk2(float x, float y) {
    ull r;
    asm("mov.b64 %0, {%1, %2};" : "=l"(r)
        : "r"(__float_as_uint(x)), "r"(__float_as_uint(y)));
    return r;
}

// ---------------- warp MMA: m16n8k16 bf16 (baseline PTX, sm_80+; VALIDATED R16) ----
__device__ __forceinline__ void mma16816(float* c, const uint32_t* a, const uint32_t* b)
{
    asm volatile(
        "mma.sync.aligned.m16n8k16.row.col.f32.bf16.bf16.f32 "
        "{%0,%1,%2,%3}, {%4,%5,%6,%7}, {%8,%9}, {%0,%1,%2,%3};"
        : "+f"(c[0]), "+f"(c[1]), "+f"(c[2]), "+f"(c[3])
        : "r"(a[0]), "r"(a[1]), "r"(a[2]), "r"(a[3]), "r"(b[0]), "r"(b[1]));
}

__device__ __forceinline__ uint32_t pkbf(float x, float y) {
    __nv_bfloat162 h = __floats2bfloat162_rn(x, y);
    return *(uint32_t*)&h;
}

// ---------------- device scratch (allocation-free) ----------------
__device__ float g_xT[(size_t)M_TOT*I_];        // 16 MB  transposed x -> [s*B+b][i]
__device__ float g_xpT[(size_t)G3H*M_TOT];      // 201 MB xproj TRANSPOSED [col][s*B+b]
__device__ float g_hs[(size_t)M_TOT*H_];        // 64 MB  layer output sequence [s*B+b][h]
__device__ __nv_bfloat16 g_A0[(size_t)M_TOT*H_];  // A split hi (GEMM)
__device__ __nv_bfloat16 g_A1[(size_t)M_TOT*H_];  // A split lo
__device__ __nv_bfloat16 g_W0[(size_t)G3H*H_];    // W split hi
__device__ __nv_bfloat16 g_W1[(size_t)G3H*H_];    // W split lo
// recurrence fragment arrays: [kappa=k/16 (64)][mu=b/16 (2)][lane (32)] x uint4
__device__ uint4 g_hF0 [64*2*32];
__device__ uint4 g_hF1 [64*2*32];
__device__ uint4 g_rhF0[64*2*32];
__device__ uint4 g_rhF1[64*2*32];
__device__ unsigned int g_barcount;
__device__ unsigned int g_bargen;

// ---------------- grid-wide barrier (PROVEN atomic version — do not touch) ----------------
__device__ __forceinline__ void grid_barrier()
{
    __syncthreads();
    if (threadIdx.x == 0) {
        unsigned int gen = *(volatile unsigned int*)&g_bargen;
        __threadfence();
        if (atomicAdd(&g_barcount, 1u) == gridDim.x - 1u) {
            g_barcount = 0u;
            __threadfence();
            atomicAdd(&g_bargen, 1u);
        } else {
            while (*(volatile unsigned int*)&g_bargen == gen) { __nanosleep(32); }
        }
        __threadfence();
    }
    __syncthreads();
}

// ---------------- transpose x[b][s][i] -> xT[(s*B+b)][i] ----------------
__global__ void transpose_kernel(const float4* __restrict__ x, float4* __restrict__ xT)
{
    int idx = blockIdx.x * blockDim.x + threadIdx.x;
    int i4 = idx & 63;
    int m  = idx >> 6;
    int b  = m & 31;
    int s  = m >> 5;
    xT[idx] = x[(size_t)(b * S_ + s) * 64 + i4];
}

// ---------------- bf16 two-component split ----------------
__global__ void split_kernel(const float* __restrict__ src,
                             __nv_bfloat16* __restrict__ d0,
                             __nv_bfloat16* __restrict__ d1, int n)
{
    int i = blockIdx.x * blockDim.x + threadIdx.x;
    if (i < n) {
        float x = src[i];
        __nv_bfloat16 b0 = __float2bfloat16(x);
        float r = x - __bfloat162float(b0);
        d0[i] = b0;
        d1[i] = __float2bfloat16(r);
    }
}

// ---------------- tensor-core GEMM via mma.sync bf16-split (VALIDATED R16) ----------
__global__ void __launch_bounds__(256) gemm_mma_kernel(
    const __nv_bfloat16* __restrict__ A0, const __nv_bfloat16* __restrict__ A1,
    const __nv_bfloat16* __restrict__ W0, const __nv_bfloat16* __restrict__ W1,
    const float* __restrict__ bias, float* __restrict__ C,
    int K, int mode)
{
    __shared__ __nv_bfloat16 sA0[128][40];
    __shared__ __nv_bfloat16 sA1[128][40];
    __shared__ __nv_bfloat16 sW0[128][40];
    __shared__ __nv_bfloat16 sW1[128][40];

    const int tid  = threadIdx.x;
    const int wid  = tid >> 5;
    const int lane = tid & 31;
    const int wm   = wid >> 2;
    const int wn   = wid & 3;
    const int g    = lane >> 2;
    const int t    = lane & 3;
    const int mbase = blockIdx.y * 128;
    const int nbase = blockIdx.x * 128;

    float c[4][4][4];
#pragma unroll
    for (int mi = 0; mi < 4; mi++)
#pragma unroll
        for (int ni = 0; ni < 4; ni++)
#pragma unroll
            for (int f = 0; f < 4; f++) c[mi][ni][f] = 0.f;

    for (int kt = 0; kt < K; kt += 32) {
        __syncthreads();
#pragma unroll
        for (int i = 0; i < 4; i++) {
            int v   = tid + i * 256;
            int row = v >> 3;
            int cv  = v & 7;
            size_t goff = (size_t)(mbase + row) * K + kt + cv * 4;
            size_t woff = (size_t)(nbase + row) * K + kt + cv * 4;
            *(uint2*)&sA0[row][cv * 4] = *(const uint2*)(A0 + goff);
            *(uint2*)&sA1[row][cv * 4] = *(const uint2*)(A1 + goff);
            *(uint2*)&sW0[row][cv * 4] = *(const uint2*)(W0 + woff);
            *(uint2*)&sW1[row][cv * 4] = *(const uint2*)(W1 + woff);
        }
        __syncthreads();

#pragma unroll
        for (int ks = 0; ks < 2; ks++) {
            const int kk = ks * 16 + t * 2;
            uint32_t w0f[4][2], w1f[4][2];
#pragma unroll
            for (int ni = 0; ni < 4; ni++) {
                int nr = wn * 32 + ni * 8 + g;
                w0f[ni][0] = *(const uint32_t*)&sW0[nr][kk];
                w0f[ni][1] = *(const uint32_t*)&sW0[nr][kk + 8];
                w1f[ni][0] = *(const uint32_t*)&sW1[nr][kk];
                w1f[ni][1] = *(const uint32_t*)&sW1[nr][kk + 8];
            }
#pragma unroll
            for (int mi = 0; mi < 4; mi++) {
                int mr = wm * 64 + mi * 16 + g;
                uint32_t a0f[4], a1f[4];
                a0f[0] = *(const uint32_t*)&sA0[mr][kk];
                a0f[1] = *(const uint32_t*)&sA0[mr + 8][kk];
                a0f[2] = *(const uint32_t*)&sA0[mr][kk + 8];
                a0f[3] = *(const uint32_t*)&sA0[mr + 8][kk + 8];
                a1f[0] = *(const uint32_t*)&sA1[mr][kk];
                a1f[1] = *(const uint32_t*)&sA1[mr + 8][kk];
                a1f[2] = *(const uint32_t*)&sA1[mr][kk + 8];
                a1f[3] = *(const uint32_t*)&sA1[mr + 8][kk + 8];
#pragma unroll
                for (int ni = 0; ni < 4; ni++) {
                    mma16816(c[mi][ni], a0f, w0f[ni]);
                    mma16816(c[mi][ni], a0f, w1f[ni]);
                    mma16816(c[mi][ni], a1f, w0f[ni]);
                }
            }
        }
    }

#pragma unroll
    for (int mi = 0; mi < 4; mi++) {
#pragma unroll
        for (int ni = 0; ni < 4; ni++) {
            int mr = mbase + wm * 64 + mi * 16 + g;
            int nc = nbase + wn * 32 + ni * 8 + t * 2;
            float b0v = __ldg(&bias[nc]);
            float b1v = __ldg(&bias[nc + 1]);
            if (mode == 0) {
                C[(size_t)nc * M_TOT + mr]           = c[mi][ni][0] + b0v;
                C[(size_t)(nc + 1) * M_TOT + mr]     = c[mi][ni][1] + b1v;
                C[(size_t)nc * M_TOT + mr + 8]       = c[mi][ni][2] + b0v;
                C[(size_t)(nc + 1) * M_TOT + mr + 8] = c[mi][ni][3] + b1v;
            } else {
                int b0i = mr & 31, s0 = mr >> 5;
                int b1i = (mr + 8) & 31, s1 = (mr + 8) >> 5;
                float* d0 = C + (size_t)((b0i << 9) + s0) * O_;
                float* d1 = C + (size_t)((b1i << 9) + s1) * O_;
                d0[nc]     = c[mi][ni][0] + b0v;
                d0[nc + 1] = c[mi][ni][1] + b1v;
                d1[nc]     = c[mi][ni][2] + b0v;
                d1[nc + 1] = c[mi][ni][3] + b1v;
            }
        }
    }
}

// ---- fragment-layout scatter write of one bf16-split value (b, j) ----
__device__ __forceinline__ void frag_write(uint4* F0, uint4* F1, int b, int j, float v)
{
    int kap = j >> 4, mu = b >> 4;
    int r = b & 15, cb = j & 15;
    int reg = (r >> 3) + ((cb >> 3) << 1);
    int ln  = (r & 7) * 4 + ((cb & 7) >> 1);
    int off = (((kap * 2 + mu) * 32 + ln) << 3) + reg * 2 + (cb & 1);
    __nv_bfloat16 hi = __float2bfloat16(v);
    __nv_bfloat16 lo = __float2bfloat16(v - __bfloat162float(hi));
    ((__nv_bfloat16*)F0)[off] = hi;
    ((__nv_bfloat16*)F1)[off] = lo;
}

// ---------------- persistent GRU recurrence: tensor-core edition ----------------
// 128 CTAs, 512 threads = 16 warps. CTA owns cols [cta*8, cta*8+8) of z, r, g.
// Warp w = k-slice [w*64, w*64+64) = kappa in {4w..4w+3}.
// h / r*h as bf16-split fragment arrays; Wh pre-split+fragment-packed in smem.
// Reduction/epilogue machinery identical to the proven FFMA2 version.
__global__ void __launch_bounds__(512, 1) gru_rec_kernel(
    const float* __restrict__ Wh,      // [3H][H]
    const float* __restrict__ xpT,     // [3H][S*B] (bias folded in)
    float*       __restrict__ hs,      // [S*B][H]
    const float* __restrict__ h0,      // [B][L][H]
    int layer,
    float*       __restrict__ hlast)   // d_out + B*S*O : [B][L][H]
{
    extern __shared__ float sh[];
    uint2* ws  = (uint2*)sh;           // A-region 8192 + B-region 4096 uint2 = 96 KB
    float* red = sh + 24576;           // [16][32][17] partials    34 KB
    __shared__ float s_z[B_ * 8];
    __shared__ float s_h[B_ * 8];

    const int tid  = threadIdx.x;
    const int cta  = blockIdx.x;
    const int w    = tid >> 5;
    const int lane = tid & 31;
    const int g    = lane >> 2;
    const int t    = lane & 3;
    const int j0   = cta * 8;

    // ---- preload weights: split to bf16 hi/lo, packed in B-fragment order ----
    for (int it = 0; it < 24; it++) {
        int flat = tid + it * 512;     // 12288 total
        int row, k, sp, dst;
        if (flat < 8192) {
            int ln = flat & 31;
            sp = (flat >> 5) & 1;
            int ks = (flat >> 6) & 3;
            int ni = (flat >> 8) & 1;
            int wp = flat >> 9;
            row = (ni ? H_ : 0) + j0 + (ln >> 2);
            k = wp * 64 + ks * 16 + (ln & 3) * 2;
            dst = flat;
        } else {
            int e = flat - 8192;
            int ln = e & 31;
            sp = (e >> 5) & 1;
            int ks = (e >> 6) & 3;
            int wp = e >> 8;
            row = 2 * H_ + j0 + (ln >> 2);
            k = wp * 64 + ks * 16 + (ln & 3) * 2;
            dst = flat;
        }
        const float* src = Wh + (size_t)row * H_;
        float v0 = __ldg(src + k),     v1 = __ldg(src + k + 1);
        float v2 = __ldg(src + k + 8), v3 = __ldg(src + k + 9);
        if (sp == 0) {
            ws[dst] = make_uint2(pkbf(v0, v1), pkbf(v2, v3));
        } else {
            float h0v = __bfloat162float(__float2bfloat16(v0));
            float h1v = __bfloat162float(__float2bfloat16(v1));
            float h2v = __bfloat162float(__float2bfloat16(v2));
            float h3v = __bfloat162float(__float2bfloat16(v3));
            ws[dst] = make_uint2(pkbf(v0 - h0v, v1 - h1v), pkbf(v2 - h2v, v3 - h3v));
        }
    }

    // ---- init hidden state fragments + s_h ----
    {
        int i = cta * 512 + tid;
        if (i < B_ * H_) {
            int b = i >> 10, j = i & 1023;
            frag_write(g_hF0, g_hF1, b, j, h0[(b * L_ + layer) * H_ + j]);
        }
        if (w < 8) s_h[lane * 8 + w] = h0[(lane * L_ + layer) * H_ + j0 + w];
    }
    grid_barrier();

    const float* xpColA = xpT + (size_t)((w < 8) ? (j0 + w) : (H_ + j0 + (w - 8))) * M_TOT;
    const float* xpColB = (w < 8) ? (xpT + (size_t)(2 * H_ + j0 + w) * M_TOT) : xpT;

    for (int s = 0; s < S_; s++) {
        const int m = s * B_ + lane;
        float xpA = __ldg(xpColA + m);
        float xpB = (w < 8) ? __ldg(xpColB + m) : 0.f;

        // ---- phase A: 48 MMAs (2m x 2n x 4k x 3 splits) on h fragments ----
        {
            float c[2][2][4];
#pragma unroll
            for (int mu = 0; mu < 2; mu++)
#pragma unroll
                for (int ni = 0; ni < 2; ni++)
#pragma unroll
                    for (int f = 0; f < 4; f++) c[mu][ni][f] = 0.f;

#pragma unroll 1
            for (int ks = 0; ks < 4; ks++) {
                const int kidx = (w * 4 + ks) * 2;
                uint4 a0h = __ldcg(&g_hF0[(kidx + 0) * 32 + lane]);
                uint4 a1h = __ldcg(&g_hF0[(kidx + 1) * 32 + lane]);
                uint4 a0l = __ldcg(&g_hF1[(kidx + 0) * 32 + lane]);
                uint4 a1l = __ldcg(&g_hF1[(kidx + 1) * 32 + lane]);
#pragma unroll
                for (int ni = 0; ni < 2; ni++) {
                    uint2 w0 = ws[((((w * 2 + ni) * 4 + ks) * 2) + 0) * 32 + lane];
                    uint2 w1 = ws[((((w * 2 + ni) * 4 + ks) * 2) + 1) * 32 + lane];
                    mma16816(c[0][ni], (const uint32_t*)&a0h, (const uint32_t*)&w0);
                    mma16816(c[0][ni], (const uint32_t*)&a0h, (const uint32_t*)&w1);
                    mma16816(c[0][ni], (const uint32_t*)&a0l, (const uint32_t*)&w0);
                    mma16816(c[1][ni], (const uint32_t*)&a1h, (const uint32_t*)&w0);
                    mma16816(c[1][ni], (const uint32_t*)&a1h, (const uint32_t*)&w1);
                    mma16816(c[1][ni], (const uint32_t*)&a1l, (const uint32_t*)&w0);
                }
            }
            // scatter into red[(j*32+b)*17 + w]
#pragma unroll
            for (int mu = 0; mu < 2; mu++)
#pragma unroll
                for (int ni = 0; ni < 2; ni++)
#pragma unroll
                    for (int f = 0; f < 4; f++) {
                        int j = ni * 8 + t * 2 + (f & 1);
                        int b = mu * 16 + g + ((f >> 1) << 3);
                        red[(j * 32 + b) * 17 + w] = c[mu][ni][f];
                    }
        }
        __syncthreads();

        // ---- reduce + gate epilogue: thread (c=w, b=lane)  [PROVEN] ----
        {
            const float* rp = red + (w * 32 + lane) * 17;
            float sum = xpA;
#pragma unroll
            for (int tr = 0; tr < 16; tr++) sum += rp[tr];
            float sg = 1.f / (1.f + expf(-sum));
            if (w < 8) {
                s_z[lane * 8 + w] = sg;
            } else {
                int cc = w - 8;
                frag_write(g_rhF0, g_rhF1, lane, j0 + cc, sg * s_h[lane * 8 + cc]);
            }
        }
        grid_barrier();

        // ---- phase B: 24 MMAs (2m x 1n x 4k x 3 splits) on rh fragments ----
        {
            float c[2][4];
#pragma unroll
            for (int mu = 0; mu < 2; mu++)
#pragma unroll
                for (int f = 0; f < 4; f++) c[mu][f] = 0.f;

#pragma unroll 1
            for (int ks = 0; ks < 4; ks++) {
                const int kidx = (w * 4 + ks) * 2;
                uint4 a0h = __ldcg(&g_rhF0[(kidx + 0) * 32 + lane]);
                uint4 a1h = __ldcg(&g_rhF0[(kidx + 1) * 32 + lane]);
                uint4 a0l = __ldcg(&g_rhF1[(kidx + 0) * 32 + lane]);
                uint4 a1l = __ldcg(&g_rhF1[(kidx + 1) * 32 + lane]);
                uint2 w0 = ws[8192 + (((w * 4 + ks) * 2) + 0) * 32 + lane];
                uint2 w1 = ws[8192 + (((w * 4 + ks) * 2) + 1) * 32 + lane];
                mma16816(c[0], (const uint32_t*)&a0h, (const uint32_t*)&w0);
                mma16816(c[0], (const uint32_t*)&a0h, (const uint32_t*)&w1);
                mma16816(c[0], (const uint32_t*)&a0l, (const uint32_t*)&w0);
                mma16816(c[1], (const uint32_t*)&a1h, (const uint32_t*)&w0);
                mma16816(c[1], (const uint32_t*)&a1h, (const uint32_t*)&w1);
                mma16816(c[1], (const uint32_t*)&a1l, (const uint32_t*)&w0);
            }
#pragma unroll
            for (int mu = 0; mu < 2; mu++)
#pragma unroll
                for (int f = 0; f < 4; f++) {
                    int j = t * 2 + (f & 1);
                    int b = mu * 16 + g + ((f >> 1) << 3);
                    red[(j * 32 + b) * 17 + w] = c[mu][f];
                }
        }
        __syncthreads();

        // ---- reduce + h update: thread (c=w<8, b=lane)  [PROVEN] ----
        if (w < 8) {
            const float* rp = red + (w * 32 + lane) * 17;
            float sum = xpB;
#pragma unroll
            for (int tr = 0; tr < 16; tr++) sum += rp[tr];
            float gg = tanhf(sum);
            float zz = s_z[lane * 8 + w];
            float ho = s_h[lane * 8 + w];
            float hn = zz * ho + (1.f - zz) * gg;
            int j = j0 + w;
            s_h[lane * 8 + w] = hn;
            frag_write(g_hF0, g_hF1, lane, j, hn);
            hs[(size_t)(s * B_ + lane) * H_ + j] = hn;
            if (s == S_ - 1) hlast[(size_t)(lane * L_ + layer) * H_ + j] = hn;
        }
        grid_barrier();
    }
}

// ---------------- host launch ----------------
extern "C" void kernel_launch(void* const* d_in, const int* in_sizes, int n_in,
                              void* d_out, int out_size)
{
    const float* x    = (const float*)d_in[0];
    const float* h0   = (const float*)d_in[1];
    const float* Wx0  = (const float*)d_in[2];
    const float* Wh0  = (const float*)d_in[3];
    const float* bh0  = (const float*)d_in[4];
    const float* Wx   = (const float*)d_in[5];
    const float* Wh   = (const float*)d_in[6];
    const float* bh   = (const float*)d_in[7];
    const float* Wout = (const float*)d_in[8];
    const float* bout = (const float*)d_in[9];

    float* out = (float*)d_out;
    float* hid = out + (size_t)B_ * S_ * O_;

    float *p_xT, *p_xpT, *p_hs;
    __nv_bfloat16 *p_A0, *p_A1, *p_W0, *p_W1;
    cudaGetSymbolAddress((void**)&p_xT, g_xT);
    cudaGetSymbolAddress((void**)&p_xpT, g_xpT);
    cudaGetSymbolAddress((void**)&p_hs, g_hs);
    cudaGetSymbolAddress((void**)&p_A0, g_A0);
    cudaGetSymbolAddress((void**)&p_A1, g_A1);
    cudaGetSymbolAddress((void**)&p_W0, g_W0);
    cudaGetSymbolAddress((void**)&p_W1, g_W1);

    const int rec_smem = 24576 * 4 + 16 * 32 * 17 * 4;   // 133120
    cudaFuncSetAttribute(gru_rec_kernel,
                         cudaFuncAttributeMaxDynamicSharedMemorySize, rec_smem);

    // 1) transpose x -> [s*B+b][i]
    transpose_kernel<<<4096, 256>>>((const float4*)x, (float4*)p_xT);

    // 2) layer 0
    split_kernel<<<(M_TOT * I_ + 255) / 256, 256>>>(p_xT, p_A0, p_A1, M_TOT * I_);
    split_kernel<<<(G3H * I_ + 255) / 256, 256>>>(Wx0, p_W0, p_W1, G3H * I_);
    gemm_mma_kernel<<<dim3(G3H / 128, M_TOT / 128), 256>>>(
        p_A0, p_A1, p_W0, p_W1, bh0, p_xpT, I_, 0);
    gru_rec_kernel<<<NCTA_REC, 512, rec_smem>>>(Wh0, p_xpT, p_hs, h0, 0, hid);

    // 3) layer 1
    split_kernel<<<(M_TOT * H_ + 255) / 256, 256>>>(p_hs, p_A0, p_A1, M_TOT * H_);
    split_kernel<<<(G3H * H_ + 255) / 256, 256>>>(Wx, p_W0, p_W1, G3H * H_);
    gemm_mma_kernel<<<dim3(G3H / 128, M_TOT / 128), 256>>>(
        p_A0, p_A1, p_W0, p_W1, bh, p_xpT, H_, 0);
    gru_rec_kernel<<<NCTA_REC, 512, rec_smem>>>(Wh, p_xpT, p_hs, h0, 1, hid);

    // 4) layer 2
    split_kernel<<<(M_TOT * H_ + 255) / 256, 256>>>(p_hs, p_A0, p_A1, M_TOT * H_);
    split_kernel<<<(G3H * H_ + 255) / 256, 256>>>(Wx + (size_t)3 * H_ * H_, p_W0, p_W1, G3H * H_);
    gemm_mma_kernel<<<dim3(G3H / 128, M_TOT / 128), 256>>>(
        p_A0, p_A1, p_W0, p_W1, bh + 3 * H_, p_xpT, H_, 0);
    gru_rec_kernel<<<NCTA_REC, 512, rec_smem>>>(
        Wh + (size_t)3 * H_ * H_, p_xpT, p_hs, h0, 2, hid);

    // 5) output head -> d_out [B,S,O]
    split_kernel<<<(M_TOT * H_ + 255) / 256, 256>>>(p_hs, p_A0, p_A1, M_TOT * H_);
    split_kernel<<<(O_ * H_ + 255) / 256, 256>>>(Wout, p_W0, p_W1, O_ * H_);
    gemm_mma_kernel<<<dim3(O_ / 128, M_TOT / 128), 256>>>(
        p_A0, p_A1, p_W0, p_W1, bout, out, H_, 1);
}